// round 6
// baseline (speedup 1.0000x reference)
#include <cuda_runtime.h>
#include <cuda_fp16.h>
#include <cstdint>

// Problem constants
#define Bq 8
#define Sq 4096
#define Dq 768
#define Hq 12
#define DHq 64
#define Mq (Bq * Sq)          // 32768 rows

// int8 GEMM tiling (mma.sync m16n8k32 s8 -> s32)
#define BM 128
#define BN 128
#define BK 64                 // int8 K elements per chunk
#define NCHUNK 12             // 768/64
#define ROWB 80               // smem row stride bytes (64 + 16 pad)
#define MAT_B (128 * ROWB)    // 10240 bytes per matrix tile
#define STAGE_B (4 * MAT_B)   // A0,A1,B0,B1 = 40960
#define NSTAGE 2
#define GEMM_SMEM (NSTAGE * STAGE_B)   // 81920 -> 2 CTAs/SM

#define QMAX 16256.0f         // 127*128

// ---------------------------------------------------------------------------
// Scratch (device globals)
// ---------------------------------------------------------------------------
__device__ float g_Q[(size_t)Mq * Dq];
__device__ float g_K[(size_t)Mq * Dq];
__device__ float g_V[(size_t)Mq * Dq];
__device__ float g_att[(size_t)Mq * Dq];
__device__ float g_Y[(size_t)Mq * Dq];
__device__ int8_t g_xq0[(size_t)Mq * Dq];
__device__ int8_t g_xq1[(size_t)Mq * Dq];
__device__ float  g_xsc[Mq];
__device__ int8_t g_aq0[(size_t)Mq * Dq];
__device__ int8_t g_aq1[(size_t)Mq * Dq];
__device__ float  g_asc[Mq];
__device__ unsigned int g_amax[Mq];
__device__ int8_t g_wq0[(size_t)4 * Dq * Dq];   // transposed [n][k]; rows: Wq|Wk|Wv|Wo
__device__ int8_t g_wq1[(size_t)4 * Dq * Dq];
__device__ float  g_wsc[4 * Dq];
__device__ unsigned int g_wmax[4 * Dq];

// ---------------------------------------------------------------------------
// PTX helpers
// ---------------------------------------------------------------------------
__device__ __forceinline__ uint32_t smem_u32(const void* p) {
    uint32_t a;
    asm("{ .reg .u64 t; cvta.to.shared.u64 t, %1; cvt.u32.u64 %0, t; }" : "=r"(a) : "l"(p));
    return a;
}
__device__ __forceinline__ void cp16(uint32_t dst, const void* src) {
    asm volatile("cp.async.cg.shared.global [%0], [%1], 16;" :: "r"(dst), "l"(src) : "memory");
}
__device__ __forceinline__ void cp_commit() { asm volatile("cp.async.commit_group;" ::: "memory"); }
__device__ __forceinline__ void cp_wait0()  { asm volatile("cp.async.wait_group 0;" ::: "memory"); }

__device__ __forceinline__ void ldsm_x4(uint32_t (&r)[4], uint32_t addr) {
    asm volatile("ldmatrix.sync.aligned.m8n8.x4.shared.b16 {%0,%1,%2,%3}, [%4];"
                 : "=r"(r[0]), "=r"(r[1]), "=r"(r[2]), "=r"(r[3]) : "r"(addr));
}
// D += A(s8 m16k32) * B(s8 n8k32), s32 accumulate
__device__ __forceinline__ void imma(int (&d)[4], const uint32_t (&a)[4],
                                     uint32_t b0, uint32_t b1) {
    asm volatile("mma.sync.aligned.m16n8k32.row.col.s32.s8.s8.s32 "
                 "{%0,%1,%2,%3}, {%4,%5,%6,%7}, {%8,%9}, {%0,%1,%2,%3};"
                 : "+r"(d[0]), "+r"(d[1]), "+r"(d[2]), "+r"(d[3])
                 : "r"(a[0]), "r"(a[1]), "r"(a[2]), "r"(a[3]), "r"(b0), "r"(b1));
}

// ---------------------------------------------------------------------------
// Row quantizer (with block reduce): per-row absmax -> 2-digit int8
// ---------------------------------------------------------------------------
__global__ void __launch_bounds__(256) quant_rows_kernel(
    const float* __restrict__ src, int8_t* __restrict__ q0,
    int8_t* __restrict__ q1, float* __restrict__ scl)
{
    const int row = blockIdx.x;
    const int tid = threadIdx.x;
    const float* s = src + (size_t)row * Dq;

    float v[3], mx = 0.f;
    #pragma unroll
    for (int j = 0; j < 3; j++) {
        v[j] = s[tid + j * 256];
        mx = fmaxf(mx, fabsf(v[j]));
    }
    #pragma unroll
    for (int o = 16; o > 0; o >>= 1)
        mx = fmaxf(mx, __shfl_xor_sync(0xFFFFFFFFu, mx, o));
    __shared__ float rm[8];
    if ((tid & 31) == 0) rm[tid >> 5] = mx;
    __syncthreads();
    mx = fmaxf(fmaxf(fmaxf(rm[0], rm[1]), fmaxf(rm[2], rm[3])),
               fmaxf(fmaxf(rm[4], rm[5]), fmaxf(rm[6], rm[7])));

    const float inv = (mx > 0.f) ? (QMAX / mx) : 0.f;
    if (tid == 0) scl[row] = (mx > 0.f) ? (mx / QMAX) : 0.f;

    #pragma unroll
    for (int j = 0; j < 3; j++) {
        const int c = tid + j * 256;
        const int n = __float2int_rn(v[j] * inv);
        const int a0 = (n + 64) >> 7;
        const int a1 = n - (a0 << 7);
        q0[(size_t)row * Dq + c] = (int8_t)a0;
        q1[(size_t)row * Dq + c] = (int8_t)a1;
    }
}

// ---------------------------------------------------------------------------
// Elementwise quantizer using precomputed absmax (from attention atomics)
// ---------------------------------------------------------------------------
__global__ void __launch_bounds__(256) quant_att_kernel(
    const float* __restrict__ src, int8_t* __restrict__ q0,
    int8_t* __restrict__ q1, float* __restrict__ scl)
{
    const int row = blockIdx.x;
    const int tid = threadIdx.x;
    const float mx = __uint_as_float(g_amax[row]);
    const float inv = (mx > 0.f) ? (QMAX / mx) : 0.f;
    if (tid == 0) scl[row] = (mx > 0.f) ? (mx / QMAX) : 0.f;

    const float* s = src + (size_t)row * Dq;
    #pragma unroll
    for (int j = 0; j < 3; j++) {
        const int c = tid + j * 256;
        const int n = __float2int_rn(s[c] * inv);
        const int a0 = (n + 64) >> 7;
        const int a1 = n - (a0 << 7);
        q0[(size_t)row * Dq + c] = (int8_t)a0;
        q1[(size_t)row * Dq + c] = (int8_t)a1;
    }
}

__global__ void __launch_bounds__(256) zero_amax_kernel() {
    const int i = blockIdx.x * 256 + threadIdx.x;
    if (i < Mq) g_amax[i] = 0u;
}

// ---------------------------------------------------------------------------
// Weight absmax per output column (atomicMax on positive float bits)
// ---------------------------------------------------------------------------
__global__ void __launch_bounds__(256) wmax_zero_kernel() {
    const int i = blockIdx.x * 256 + threadIdx.x;
    if (i < 4 * Dq) g_wmax[i] = 0u;
}
__global__ void __launch_bounds__(256) wmax_kernel(
    const float* __restrict__ Wq, const float* __restrict__ Wk,
    const float* __restrict__ Wv, const float* __restrict__ Wo)
{
    const int w = blockIdx.z;
    const float* W = (w == 0) ? Wq : (w == 1) ? Wk : (w == 2) ? Wv : Wo;
    const int n = blockIdx.x * 256 + threadIdx.x;
    const int k0 = blockIdx.y * 96;
    float mx = 0.f;
    for (int j = 0; j < 96; j++)
        mx = fmaxf(mx, fabsf(W[(size_t)(k0 + j) * Dq + n]));
    atomicMax(&g_wmax[w * Dq + n], __float_as_uint(mx));
}

// ---------------------------------------------------------------------------
// Weight quantize + transpose: out[n][k] digits
// ---------------------------------------------------------------------------
__global__ void __launch_bounds__(256) wquant_kernel(
    const float* __restrict__ Wq, const float* __restrict__ Wk,
    const float* __restrict__ Wv, const float* __restrict__ Wo)
{
    __shared__ float t[32][33];
    const int w = blockIdx.z;
    const float* W = (w == 0) ? Wq : (w == 1) ? Wk : (w == 2) ? Wv : Wo;
    const int n0 = blockIdx.x * 32, k0 = blockIdx.y * 32;
    const int tx = threadIdx.x & 31, ty = threadIdx.x >> 5;

    #pragma unroll
    for (int i = 0; i < 4; i++)
        t[ty + i * 8][tx] = W[(size_t)(k0 + ty + i * 8) * Dq + n0 + tx];
    __syncthreads();
    #pragma unroll
    for (int i = 0; i < 4; i++) {
        const int n = n0 + ty + i * 8;
        const float mx = __uint_as_float(g_wmax[w * Dq + n]);
        const float inv = (mx > 0.f) ? (QMAX / mx) : 0.f;
        if (k0 == 0 && tx == 0)
            g_wsc[w * Dq + n] = (mx > 0.f) ? (mx / QMAX) : 0.f;
        const float val = t[tx][ty + i * 8];        // W[k0+tx][n]
        const int q = __float2int_rn(val * inv);
        const int a0 = (q + 64) >> 7;
        const int a1 = q - (a0 << 7);
        const size_t o = (size_t)(w * Dq + n) * Dq + k0 + tx;
        g_wq0[o] = (int8_t)a0;
        g_wq1[o] = (int8_t)a1;
    }
}

// ---------------------------------------------------------------------------
// int8 tensor-core GEMM: C = A @ W^T, 2-digit emulation, 3 products.
// 2-stage pipeline, 2 CTAs/SM. Next stage's load is issued after the
// barrier that retires the previous compute on that buffer, before this
// chunk's compute -> copy/compute overlap with only 2 stages.
// mode 0: outputs Q|K|V (+bias), grid (18, 256)
// mode 1: g_Y = C + bo + resid, grid (6, 256)
// ---------------------------------------------------------------------------
__global__ void __launch_bounds__(256, 2) ig_gemm_kernel(
    const int8_t* __restrict__ Aq0, const int8_t* __restrict__ Aq1,
    const float* __restrict__ Asc,
    const float* __restrict__ bias_a, const float* __restrict__ bias_b,
    const float* __restrict__ bias_c, const float* __restrict__ resid,
    int wbase, int mode)
{
    extern __shared__ __align__(128) char smem_raw[];
    const uint32_t base = smem_u32(smem_raw);

    const int tid  = threadIdx.x;
    const int wid  = tid >> 5;
    const int lane = tid & 31;
    const int m0 = blockIdx.y * BM;
    const int bx = blockIdx.x;
    const int nrow0 = wbase + bx * BN;

    const int wm0 = (wid & 3) * 32;          // 4 warps in M
    const int wn0 = (wid >> 2) * 64;         // 2 warps in N

    auto load_stage = [&](int c, int s) {
        const int k0 = c * BK;
        const uint32_t sb = base + (uint32_t)s * STAGE_B;
        #pragma unroll
        for (int half = 0; half < 2; half++) {
            const int u = tid + half * 256;          // 0..511
            const int row = u >> 2, seg = (u & 3) * 16;
            const uint32_t so = (uint32_t)(row * ROWB + seg);
            cp16(sb + 0 * MAT_B + so, Aq0 + (size_t)(m0 + row) * Dq + k0 + seg);
            cp16(sb + 1 * MAT_B + so, Aq1 + (size_t)(m0 + row) * Dq + k0 + seg);
            cp16(sb + 2 * MAT_B + so, g_wq0 + (size_t)(nrow0 + row) * Dq + k0 + seg);
            cp16(sb + 3 * MAT_B + so, g_wq1 + (size_t)(nrow0 + row) * Dq + k0 + seg);
        }
        cp_commit();
    };

    int hi[2][8][4], mid[2][8][4];
    #pragma unroll
    for (int mi = 0; mi < 2; mi++)
        #pragma unroll
        for (int n8 = 0; n8 < 8; n8++)
            #pragma unroll
            for (int j = 0; j < 4; j++) { hi[mi][n8][j] = 0; mid[mi][n8][j] = 0; }

    const int lrow = (lane & 7) + ((lane >> 3) & 1) * 8;
    const int lk16 = (lane >> 4) * 16;

    load_stage(0, 0);

    for (int c = 0; c < NCHUNK; c++) {
        cp_wait0();          // only pending group is load(c)
        __syncthreads();     // all warps done with compute(c-1) on buffer (c+1)&1
        if (c + 1 < NCHUNK) load_stage(c + 1, (c + 1) & 1);   // overlaps compute(c)

        const uint32_t sb = base + (uint32_t)(c & 1) * STAGE_B;
        const uint32_t sA0 = sb, sA1 = sb + MAT_B, sB0 = sb + 2 * MAT_B, sB1 = sb + 3 * MAT_B;

        #pragma unroll
        for (int ks = 0; ks < 2; ks++) {
            const uint32_t koff = (uint32_t)(ks * 32 + lk16);
            uint32_t a0[2][4], a1[2][4];
            #pragma unroll
            for (int mi = 0; mi < 2; mi++) {
                const uint32_t ro = (uint32_t)((wm0 + mi * 16 + lrow) * ROWB) + koff;
                ldsm_x4(a0[mi], sA0 + ro);
                ldsm_x4(a1[mi], sA1 + ro);
            }
            #pragma unroll
            for (int g = 0; g < 4; g++) {
                uint32_t b0[4], b1[4];
                const uint32_t ro = (uint32_t)((wn0 + g * 16 + lrow) * ROWB) + koff;
                ldsm_x4(b0, sB0 + ro);
                ldsm_x4(b1, sB1 + ro);
                #pragma unroll
                for (int mi = 0; mi < 2; mi++) {
                    imma(hi[mi][g * 2 + 0], a0[mi], b0[0], b0[2]);
                    imma(hi[mi][g * 2 + 1], a0[mi], b0[1], b0[3]);
                    imma(mid[mi][g * 2 + 0], a0[mi], b1[0], b1[2]);
                    imma(mid[mi][g * 2 + 1], a0[mi], b1[1], b1[3]);
                    imma(mid[mi][g * 2 + 0], a1[mi], b0[0], b0[2]);
                    imma(mid[mi][g * 2 + 1], a1[mi], b0[1], b0[3]);
                }
            }
        }
    }

    // ---- epilogue ----
    float* outp;
    const float* bias;
    int n0in;
    if (mode == 0) {
        const int sel = bx / 6;
        n0in = (bx % 6) * BN;
        outp = (sel == 0) ? g_Q : (sel == 1) ? g_K : g_V;
        bias = (sel == 0) ? bias_a : (sel == 1) ? bias_b : bias_c;
    } else {
        n0in = bx * BN;
        outp = g_Y;
        bias = bias_a;
    }

    const int qr = lane >> 2;
    const int qc = (lane & 3) * 2;
    #pragma unroll
    for (int mi = 0; mi < 2; mi++) {
        #pragma unroll
        for (int half = 0; half < 2; half++) {
            const int m = m0 + wm0 + mi * 16 + qr + half * 8;
            const float sa128 = Asc[m] * 128.f;
            #pragma unroll
            for (int n8 = 0; n8 < 8; n8++) {
                const int nl = wn0 + n8 * 8 + qc;
                const float sb0 = g_wsc[nrow0 + nl] * sa128;
                const float sb1 = g_wsc[nrow0 + nl + 1] * sa128;
                const int n = n0in + nl;
                const size_t o = (size_t)m * Dq + n;
                const int t0 = hi[mi][n8][half * 2 + 0] * 128 + mid[mi][n8][half * 2 + 0];
                const int t1 = hi[mi][n8][half * 2 + 1] * 128 + mid[mi][n8][half * 2 + 1];
                float2 v;
                v.x = (float)t0 * sb0 + bias[n];
                v.y = (float)t1 * sb1 + bias[n + 1];
                if (mode == 1) {
                    v.x += resid[o];
                    v.y += resid[o + 1];
                }
                *(float2*)(outp + o) = v;
            }
        }
    }
}

// ---------------------------------------------------------------------------
// Banded attention: 2 threads per position (each owns 32 dims),
// fp16 K/V smem staging, fused absmax atomics for quantization.
// ---------------------------------------------------------------------------
#define AT_TS 128
#define AT_HALO 132
#define AT_ROWH 70            // halves per row stride (140 B -> conflict-free half2)
#define ATT_SMEM (AT_HALO * AT_ROWH * 2)   // 18480 B

__global__ void __launch_bounds__(256) attn_kernel(
    const float* __restrict__ bk, const float* __restrict__ bv)
{
    extern __shared__ __half smh[];

    const int by = blockIdx.y;
    const int b  = by / Hq;
    const int h  = by % Hq;
    const int s0 = blockIdx.x * AT_TS;

    const size_t basep = ((size_t)b * Sq) * Dq + h * DHq;
    const int tid = threadIdx.x;
    const int si  = tid >> 1;          // position within tile
    const int hh  = tid & 1;           // dim half

    // ---- stage K (fp16) ----
    {
        const float* Kg = g_K + basep;
        const float* bsrc = bk + h * DHq;
        for (int idx = tid; idx < AT_HALO * 32; idx += 256) {
            const int r = idx >> 5;
            const int c2 = (idx & 31) * 2;
            const int gs = s0 - 2 + r;
            float2 v = (gs >= 0 && gs < Sq)
                       ? *(const float2*)(Kg + (size_t)gs * Dq + c2)
                       : *(const float2*)(bsrc + c2);
            *(__half2*)&smh[r * AT_ROWH + c2] = __float22half2_rn(v);
        }
    }
    __syncthreads();

    const float* qrow = g_Q + ((size_t)b * Sq + s0 + si) * Dq + h * DHq + hh * 32;
    float2 qv[16];
    #pragma unroll
    for (int d2 = 0; d2 < 16; d2++) qv[d2] = *(const float2*)(qrow + 2 * d2);

    float sc[5];
    #pragma unroll
    for (int i = 0; i < 5; i++) {
        const __half2* krow = (const __half2*)&smh[(si + i) * AT_ROWH + hh * 32];
        float s = 0.f;
        #pragma unroll
        for (int d2 = 0; d2 < 16; d2++) {
            const float2 kf = __half22float2(krow[d2]);
            s += qv[d2].x * kf.x + qv[d2].y * kf.y;
        }
        sc[i] = s;
    }
    #pragma unroll
    for (int i = 0; i < 5; i++)
        sc[i] += __shfl_xor_sync(0xFFFFFFFFu, sc[i], 1);

    float mx = sc[0];
    #pragma unroll
    for (int i = 1; i < 5; i++) mx = fmaxf(mx, sc[i]);
    float p[5], sum = 0.f;
    #pragma unroll
    for (int i = 0; i < 5; i++) {
        p[i] = __expf((sc[i] - mx) * 0.125f);
        sum += p[i];
    }
    const float inv = 1.f / sum;
    #pragma unroll
    for (int i = 0; i < 5; i++) p[i] *= inv;

    // ---- stage V (reuse smem) ----
    __syncthreads();
    {
        const float* Vg = g_V + basep;
        const float* bsrc = bv + h * DHq;
        for (int idx = tid; idx < AT_HALO * 32; idx += 256) {
            const int r = idx >> 5;
            const int c2 = (idx & 31) * 2;
            const int gs = s0 - 2 + r;
            float2 v = (gs >= 0 && gs < Sq)
                       ? *(const float2*)(Vg + (size_t)gs * Dq + c2)
                       : *(const float2*)(bsrc + c2);
            *(__half2*)&smh[r * AT_ROWH + c2] = __float22half2_rn(v);
        }
    }
    __syncthreads();

    float2 o2[16];
    #pragma unroll
    for (int d2 = 0; d2 < 16; d2++) { o2[d2].x = 0.f; o2[d2].y = 0.f; }
    #pragma unroll
    for (int i = 0; i < 5; i++) {
        const __half2* vrow = (const __half2*)&smh[(si + i) * AT_ROWH + hh * 32];
        const float pi = p[i];
        #pragma unroll
        for (int d2 = 0; d2 < 16; d2++) {
            const float2 vf = __half22float2(vrow[d2]);
            o2[d2].x += pi * vf.x;
            o2[d2].y += pi * vf.y;
        }
    }

    const int row = b * Sq + s0 + si;
    float* orow = g_att + (size_t)row * Dq + h * DHq + hh * 32;
    float amx = 0.f;
    #pragma unroll
    for (int d2 = 0; d2 < 16; d2++) {
        *(float2*)(orow + 2 * d2) = o2[d2];
        amx = fmaxf(amx, fmaxf(fabsf(o2[d2].x), fabsf(o2[d2].y)));
    }
    atomicMax(&g_amax[row], __float_as_uint(amx));
}

// ---------------------------------------------------------------------------
// LayerNorm over last dim (768)
// ---------------------------------------------------------------------------
__global__ void __launch_bounds__(256) ln_kernel(
    const float* __restrict__ gamma, const float* __restrict__ beta,
    float* __restrict__ outp)
{
    const int row = blockIdx.x;
    const float* y = g_Y + (size_t)row * Dq;
    const int tid = threadIdx.x;

    float v[3];
    float s = 0.f, ss = 0.f;
    #pragma unroll
    for (int j = 0; j < 3; j++) {
        v[j] = y[tid + j * 256];
        s  += v[j];
        ss += v[j] * v[j];
    }
    #pragma unroll
    for (int o = 16; o > 0; o >>= 1) {
        s  += __shfl_xor_sync(0xFFFFFFFFu, s,  o);
        ss += __shfl_xor_sync(0xFFFFFFFFu, ss, o);
    }
    __shared__ float rs[8], rss[8];
    const int w = tid >> 5;
    if ((tid & 31) == 0) { rs[w] = s; rss[w] = ss; }
    __syncthreads();
    s = 0.f; ss = 0.f;
    #pragma unroll
    for (int i = 0; i < 8; i++) { s += rs[i]; ss += rss[i]; }

    const float mu   = s * (1.f / 768.f);
    const float var  = ss * (1.f / 768.f) - mu * mu;
    const float rstd = rsqrtf(var + 1e-5f);

    #pragma unroll
    for (int j = 0; j < 3; j++) {
        const int c = tid + j * 256;
        outp[(size_t)row * Dq + c] = (v[j] - mu) * rstd * gamma[c] + beta[c];
    }
}

// ---------------------------------------------------------------------------
// Launch
// ---------------------------------------------------------------------------
extern "C" void kernel_launch(void* const* d_in, const int* in_sizes, int n_in,
                              void* d_out, int out_size)
{
    const float* x     = (const float*)d_in[0];
    const float* Wq    = (const float*)d_in[1];
    const float* bq    = (const float*)d_in[2];
    const float* Wk    = (const float*)d_in[3];
    const float* bk    = (const float*)d_in[4];
    const float* Wv    = (const float*)d_in[5];
    const float* bv    = (const float*)d_in[6];
    const float* Wo    = (const float*)d_in[7];
    const float* bo    = (const float*)d_in[8];
    const float* gamma = (const float*)d_in[9];
    const float* beta  = (const float*)d_in[10];
    float* out = (float*)d_out;

    static int configured = 0;
    if (!configured) {
        cudaFuncSetAttribute(ig_gemm_kernel,
                             cudaFuncAttributeMaxDynamicSharedMemorySize, GEMM_SMEM);
        cudaFuncSetAttribute(attn_kernel,
                             cudaFuncAttributeMaxDynamicSharedMemorySize, ATT_SMEM);
        configured = 1;
    }

    int8_t *xq0, *xq1, *aq0, *aq1;
    float *xsc, *asc, *attp;
    cudaGetSymbolAddress((void**)&xq0, g_xq0);
    cudaGetSymbolAddress((void**)&xq1, g_xq1);
    cudaGetSymbolAddress((void**)&xsc, g_xsc);
    cudaGetSymbolAddress((void**)&aq0, g_aq0);
    cudaGetSymbolAddress((void**)&aq1, g_aq1);
    cudaGetSymbolAddress((void**)&asc, g_asc);
    cudaGetSymbolAddress((void**)&attp, g_att);

    // 0) quantize inputs + weights
    quant_rows_kernel<<<Mq, 256>>>(x, xq0, xq1, xsc);
    wmax_zero_kernel<<<12, 256>>>();
    wmax_kernel<<<dim3(3, 8, 4), 256>>>(Wq, Wk, Wv, Wo);
    wquant_kernel<<<dim3(24, 24, 4), 256>>>(Wq, Wk, Wv, Wo);
    zero_amax_kernel<<<Mq / 256, 256>>>();

    // 1) QKV projections (N = 2304 over 18 tiles)
    ig_gemm_kernel<<<dim3(18, Mq / BM), 256, GEMM_SMEM>>>(
        xq0, xq1, xsc, bq, bk, bv, nullptr, 0, 0);

    // 2) Banded local attention -> g_att fp32 + fused absmax
    attn_kernel<<<dim3(Sq / AT_TS, Bq * Hq), 256, ATT_SMEM>>>(bk, bv);

    // 3) quantize att (elementwise, absmax precomputed), then O projection
    quant_att_kernel<<<Mq, 256>>>(attp, aq0, aq1, asc);
    ig_gemm_kernel<<<dim3(6, Mq / BM), 256, GEMM_SMEM>>>(
        aq0, aq1, asc, bo, nullptr, nullptr, x, 3 * Dq, 1);

    // 4) LayerNorm -> d_out
    ln_kernel<<<Mq, 256>>>(gamma, beta, out);
}

// round 7
// speedup vs baseline: 1.6862x; 1.6862x over previous
#include <cuda_runtime.h>
#include <cuda_fp16.h>
#include <cstdint>

// Problem constants
#define Bq 8
#define Sq 4096
#define Dq 768
#define Hq 12
#define DHq 64
#define Mq (Bq * Sq)          // 32768 rows

// int8 GEMM tiling (mma.sync m16n8k32 s8 -> s32)
#define BM 64
#define BN 128
#define BK 64                 // int8 K elements per chunk
#define NCHUNK 12             // 768/64
// Swizzled 64B rows, no padding. seg' = seg ^ ((row>>1)&3), 16B segments.
#define MA_B  4096            // 64 rows * 64 B (per digit)
#define MB_B  8192            // 128 rows * 64 B (per digit)
#define A0_OFF 0
#define A1_OFF 4096
#define B0_OFF 8192
#define B1_OFF 16384
#define STAGE_B 24576
#define NSTAGE 3
#define GEMM_SMEM (NSTAGE * STAGE_B)   // 73728 -> 2 CTAs/SM

#define QMAX 16256.0f         // 127*128

// ---------------------------------------------------------------------------
// Scratch (device globals)
// ---------------------------------------------------------------------------
__device__ float g_Q[(size_t)Mq * Dq];
__device__ float g_K[(size_t)Mq * Dq];
__device__ float g_V[(size_t)Mq * Dq];
__device__ float g_att[(size_t)Mq * Dq];
__device__ float g_Y[(size_t)Mq * Dq];
__device__ int8_t g_xq0[(size_t)Mq * Dq];
__device__ int8_t g_xq1[(size_t)Mq * Dq];
__device__ float  g_xsc[Mq];
__device__ int8_t g_aq0[(size_t)Mq * Dq];
__device__ int8_t g_aq1[(size_t)Mq * Dq];
__device__ float  g_asc[Mq];
__device__ unsigned int g_amax[Mq];
__device__ int8_t g_wq0[(size_t)4 * Dq * Dq];   // transposed [n][k]; rows: Wq|Wk|Wv|Wo
__device__ int8_t g_wq1[(size_t)4 * Dq * Dq];
__device__ float  g_wsc[4 * Dq];
__device__ unsigned int g_wmax[4 * Dq];

// ---------------------------------------------------------------------------
// PTX helpers
// ---------------------------------------------------------------------------
__device__ __forceinline__ uint32_t smem_u32(const void* p) {
    uint32_t a;
    asm("{ .reg .u64 t; cvta.to.shared.u64 t, %1; cvt.u32.u64 %0, t; }" : "=r"(a) : "l"(p));
    return a;
}
__device__ __forceinline__ void cp16(uint32_t dst, const void* src) {
    asm volatile("cp.async.cg.shared.global [%0], [%1], 16;" :: "r"(dst), "l"(src) : "memory");
}
__device__ __forceinline__ void cp_commit() { asm volatile("cp.async.commit_group;" ::: "memory"); }
__device__ __forceinline__ void cp_wait1()  { asm volatile("cp.async.wait_group 1;" ::: "memory"); }
__device__ __forceinline__ void cp_wait0()  { asm volatile("cp.async.wait_group 0;" ::: "memory"); }

__device__ __forceinline__ void ldsm_x4(uint32_t (&r)[4], uint32_t addr) {
    asm volatile("ldmatrix.sync.aligned.m8n8.x4.shared.b16 {%0,%1,%2,%3}, [%4];"
                 : "=r"(r[0]), "=r"(r[1]), "=r"(r[2]), "=r"(r[3]) : "r"(addr));
}
// D += A(s8 m16k32) * B(s8 n8k32), s32 accumulate
__device__ __forceinline__ void imma(int (&d)[4], const uint32_t (&a)[4],
                                     uint32_t b0, uint32_t b1) {
    asm volatile("mma.sync.aligned.m16n8k32.row.col.s32.s8.s8.s32 "
                 "{%0,%1,%2,%3}, {%4,%5,%6,%7}, {%8,%9}, {%0,%1,%2,%3};"
                 : "+r"(d[0]), "+r"(d[1]), "+r"(d[2]), "+r"(d[3])
                 : "r"(a[0]), "r"(a[1]), "r"(a[2]), "r"(a[3]), "r"(b0), "r"(b1));
}

// ---------------------------------------------------------------------------
// Row quantizer (with block reduce): per-row absmax -> 2-digit int8
// ---------------------------------------------------------------------------
__global__ void __launch_bounds__(256) quant_rows_kernel(
    const float* __restrict__ src, int8_t* __restrict__ q0,
    int8_t* __restrict__ q1, float* __restrict__ scl)
{
    const int row = blockIdx.x;
    const int tid = threadIdx.x;
    const float* s = src + (size_t)row * Dq;

    float v[3], mx = 0.f;
    #pragma unroll
    for (int j = 0; j < 3; j++) {
        v[j] = s[tid + j * 256];
        mx = fmaxf(mx, fabsf(v[j]));
    }
    #pragma unroll
    for (int o = 16; o > 0; o >>= 1)
        mx = fmaxf(mx, __shfl_xor_sync(0xFFFFFFFFu, mx, o));
    __shared__ float rm[8];
    if ((tid & 31) == 0) rm[tid >> 5] = mx;
    __syncthreads();
    mx = fmaxf(fmaxf(fmaxf(rm[0], rm[1]), fmaxf(rm[2], rm[3])),
               fmaxf(fmaxf(rm[4], rm[5]), fmaxf(rm[6], rm[7])));

    const float inv = (mx > 0.f) ? (QMAX / mx) : 0.f;
    if (tid == 0) scl[row] = (mx > 0.f) ? (mx / QMAX) : 0.f;

    #pragma unroll
    for (int j = 0; j < 3; j++) {
        const int c = tid + j * 256;
        const int n = __float2int_rn(v[j] * inv);
        const int a0 = (n + 64) >> 7;
        const int a1 = n - (a0 << 7);
        q0[(size_t)row * Dq + c] = (int8_t)a0;
        q1[(size_t)row * Dq + c] = (int8_t)a1;
    }
}

// ---------------------------------------------------------------------------
// Elementwise quantizer using precomputed absmax (from attention atomics)
// ---------------------------------------------------------------------------
__global__ void __launch_bounds__(256) quant_att_kernel(
    const float* __restrict__ src, int8_t* __restrict__ q0,
    int8_t* __restrict__ q1, float* __restrict__ scl)
{
    const int row = blockIdx.x;
    const int tid = threadIdx.x;
    const float mx = __uint_as_float(g_amax[row]);
    const float inv = (mx > 0.f) ? (QMAX / mx) : 0.f;
    if (tid == 0) scl[row] = (mx > 0.f) ? (mx / QMAX) : 0.f;

    const float* s = src + (size_t)row * Dq;
    #pragma unroll
    for (int j = 0; j < 3; j++) {
        const int c = tid + j * 256;
        const int n = __float2int_rn(s[c] * inv);
        const int a0 = (n + 64) >> 7;
        const int a1 = n - (a0 << 7);
        q0[(size_t)row * Dq + c] = (int8_t)a0;
        q1[(size_t)row * Dq + c] = (int8_t)a1;
    }
}

__global__ void __launch_bounds__(256) zero_amax_kernel() {
    const int i = blockIdx.x * 256 + threadIdx.x;
    if (i < Mq) g_amax[i] = 0u;
}

// ---------------------------------------------------------------------------
// Weight absmax per output column (atomicMax on positive float bits)
// ---------------------------------------------------------------------------
__global__ void __launch_bounds__(256) wmax_zero_kernel() {
    const int i = blockIdx.x * 256 + threadIdx.x;
    if (i < 4 * Dq) g_wmax[i] = 0u;
}
__global__ void __launch_bounds__(256) wmax_kernel(
    const float* __restrict__ Wq, const float* __restrict__ Wk,
    const float* __restrict__ Wv, const float* __restrict__ Wo)
{
    const int w = blockIdx.z;
    const float* W = (w == 0) ? Wq : (w == 1) ? Wk : (w == 2) ? Wv : Wo;
    const int n = blockIdx.x * 256 + threadIdx.x;
    const int k0 = blockIdx.y * 96;
    float mx = 0.f;
    for (int j = 0; j < 96; j++)
        mx = fmaxf(mx, fabsf(W[(size_t)(k0 + j) * Dq + n]));
    atomicMax(&g_wmax[w * Dq + n], __float_as_uint(mx));
}

// ---------------------------------------------------------------------------
// Weight quantize + transpose: out[n][k] digits
// ---------------------------------------------------------------------------
__global__ void __launch_bounds__(256) wquant_kernel(
    const float* __restrict__ Wq, const float* __restrict__ Wk,
    const float* __restrict__ Wv, const float* __restrict__ Wo)
{
    __shared__ float t[32][33];
    const int w = blockIdx.z;
    const float* W = (w == 0) ? Wq : (w == 1) ? Wk : (w == 2) ? Wv : Wo;
    const int n0 = blockIdx.x * 32, k0 = blockIdx.y * 32;
    const int tx = threadIdx.x & 31, ty = threadIdx.x >> 5;

    #pragma unroll
    for (int i = 0; i < 4; i++)
        t[ty + i * 8][tx] = W[(size_t)(k0 + ty + i * 8) * Dq + n0 + tx];
    __syncthreads();
    #pragma unroll
    for (int i = 0; i < 4; i++) {
        const int n = n0 + ty + i * 8;
        const float mx = __uint_as_float(g_wmax[w * Dq + n]);
        const float inv = (mx > 0.f) ? (QMAX / mx) : 0.f;
        if (k0 == 0 && tx == 0)
            g_wsc[w * Dq + n] = (mx > 0.f) ? (mx / QMAX) : 0.f;
        const float val = t[tx][ty + i * 8];        // W[k0+tx][n]
        const int q = __float2int_rn(val * inv);
        const int a0 = (q + 64) >> 7;
        const int a1 = q - (a0 << 7);
        const size_t o = (size_t)(w * Dq + n) * Dq + k0 + tx;
        g_wq0[o] = (int8_t)a0;
        g_wq1[o] = (int8_t)a1;
    }
}

// ---------------------------------------------------------------------------
// int8 tensor-core GEMM: C[64 x 128] = A @ W^T, 2-digit emulation, 3 products.
// 3-stage cp.async pipeline (R5-proven), XOR-swizzled 64B smem rows,
// 2 CTAs/SM (72 KB smem, 64-int accumulators).
// mode 0: outputs Q|K|V (+bias), grid (18, 512)
// mode 1: g_Y = C + bo + resid, grid (6, 512)
// ---------------------------------------------------------------------------
__global__ void __launch_bounds__(256, 2) ig_gemm_kernel(
    const int8_t* __restrict__ Aq0, const int8_t* __restrict__ Aq1,
    const float* __restrict__ Asc,
    const float* __restrict__ bias_a, const float* __restrict__ bias_b,
    const float* __restrict__ bias_c, const float* __restrict__ resid,
    int wbase, int mode)
{
    extern __shared__ __align__(128) char smem_raw[];
    const uint32_t base = smem_u32(smem_raw);

    const int tid  = threadIdx.x;
    const int wid  = tid >> 5;
    const int lane = tid & 31;
    const int m0 = blockIdx.y * BM;
    const int bx = blockIdx.x;
    const int nrow0 = wbase + bx * BN;

    const int wm0 = (wid & 1) * 32;          // 2 warps in M
    const int wn0 = (wid >> 1) * 32;         // 4 warps in N

    // loader per-thread indices (swizzled 64B rows)
    const int rA   = tid >> 2;               // 0..63
    const int sgA  = tid & 3;                // 16B segment
    const uint32_t soA = (uint32_t)(rA * 64 + ((sgA ^ ((rA >> 1) & 3)) << 4));

    auto load_stage = [&](int c, int s) {
        const int k0 = c * BK;
        const uint32_t sb = base + (uint32_t)s * STAGE_B;
        // A: 64 rows x 4 segs, 1 cp16 per digit per thread
        cp16(sb + A0_OFF + soA, Aq0 + (size_t)(m0 + rA) * Dq + k0 + sgA * 16);
        cp16(sb + A1_OFF + soA, Aq1 + (size_t)(m0 + rA) * Dq + k0 + sgA * 16);
        // B: 128 rows x 4 segs, 2 halves
        #pragma unroll
        for (int half = 0; half < 2; half++) {
            const int u = tid + half * 256;
            const int rB = u >> 2, sgB = u & 3;
            const uint32_t soB = (uint32_t)(rB * 64 + ((sgB ^ ((rB >> 1) & 3)) << 4));
            cp16(sb + B0_OFF + soB, g_wq0 + (size_t)(nrow0 + rB) * Dq + k0 + sgB * 16);
            cp16(sb + B1_OFF + soB, g_wq1 + (size_t)(nrow0 + rB) * Dq + k0 + sgB * 16);
        }
        cp_commit();
    };

    int hi[2][4][4], mid[2][4][4];
    #pragma unroll
    for (int mi = 0; mi < 2; mi++)
        #pragma unroll
        for (int n8 = 0; n8 < 4; n8++)
            #pragma unroll
            for (int j = 0; j < 4; j++) { hi[mi][n8][j] = 0; mid[mi][n8][j] = 0; }

    const int lrow = (lane & 7) + ((lane >> 3) & 1) * 8;   // row within 16-row group
    const int lkseg = (lane >> 4);                          // 0 or 1 (16B k-half)

    load_stage(0, 0);
    load_stage(1, 1);

    for (int c = 0; c < NCHUNK; c++) {
        if (c + 1 < NCHUNK) cp_wait1();
        else                cp_wait0();
        __syncthreads();
        if (c + 2 < NCHUNK) load_stage(c + 2, (c + 2) % NSTAGE);

        const uint32_t sb = base + (uint32_t)(c % NSTAGE) * STAGE_B;
        const uint32_t sA0 = sb + A0_OFF, sA1 = sb + A1_OFF;
        const uint32_t sB0 = sb + B0_OFF, sB1 = sb + B1_OFF;

        #pragma unroll
        for (int ks = 0; ks < 2; ks++) {
            const int segk = ks * 2 + lkseg;               // logical 16B segment
            uint32_t a0[2][4], a1[2][4];
            #pragma unroll
            for (int mi = 0; mi < 2; mi++) {
                const int row = wm0 + mi * 16 + lrow;
                const uint32_t ro = (uint32_t)(row * 64 + ((segk ^ ((row >> 1) & 3)) << 4));
                ldsm_x4(a0[mi], sA0 + ro);
                ldsm_x4(a1[mi], sA1 + ro);
            }
            #pragma unroll
            for (int g = 0; g < 2; g++) {
                uint32_t b0[4], b1[4];
                const int row = wn0 + g * 16 + lrow;
                const uint32_t ro = (uint32_t)(row * 64 + ((segk ^ ((row >> 1) & 3)) << 4));
                ldsm_x4(b0, sB0 + ro);
                ldsm_x4(b1, sB1 + ro);
                #pragma unroll
                for (int mi = 0; mi < 2; mi++) {
                    imma(hi[mi][g * 2 + 0], a0[mi], b0[0], b0[2]);
                    imma(hi[mi][g * 2 + 1], a0[mi], b0[1], b0[3]);
                    imma(mid[mi][g * 2 + 0], a0[mi], b1[0], b1[2]);
                    imma(mid[mi][g * 2 + 1], a0[mi], b1[1], b1[3]);
                    imma(mid[mi][g * 2 + 0], a1[mi], b0[0], b0[2]);
                    imma(mid[mi][g * 2 + 1], a1[mi], b0[1], b0[3]);
                }
            }
        }
    }

    // ---- epilogue ----
    float* outp;
    const float* bias;
    int n0in;
    if (mode == 0) {
        const int sel = bx / 6;
        n0in = (bx % 6) * BN;
        outp = (sel == 0) ? g_Q : (sel == 1) ? g_K : g_V;
        bias = (sel == 0) ? bias_a : (sel == 1) ? bias_b : bias_c;
    } else {
        n0in = bx * BN;
        outp = g_Y;
        bias = bias_a;
    }

    const int qr = lane >> 2;
    const int qc = (lane & 3) * 2;
    #pragma unroll
    for (int mi = 0; mi < 2; mi++) {
        #pragma unroll
        for (int half = 0; half < 2; half++) {
            const int m = m0 + wm0 + mi * 16 + qr + half * 8;
            const float sa128 = Asc[m] * 128.f;
            #pragma unroll
            for (int n8 = 0; n8 < 4; n8++) {
                const int nl = wn0 + n8 * 8 + qc;
                const float sb0 = g_wsc[nrow0 + nl] * sa128;
                const float sb1 = g_wsc[nrow0 + nl + 1] * sa128;
                const int n = n0in + nl;
                const size_t o = (size_t)m * Dq + n;
                const int t0 = hi[mi][n8][half * 2 + 0] * 128 + mid[mi][n8][half * 2 + 0];
                const int t1 = hi[mi][n8][half * 2 + 1] * 128 + mid[mi][n8][half * 2 + 1];
                float2 v;
                v.x = (float)t0 * sb0 + bias[n];
                v.y = (float)t1 * sb1 + bias[n + 1];
                if (mode == 1) {
                    v.x += resid[o];
                    v.y += resid[o + 1];
                }
                *(float2*)(outp + o) = v;
            }
        }
    }
}

// ---------------------------------------------------------------------------
// Banded attention: 2 threads per position (each owns 32 dims),
// fp16 K/V smem staging, fused absmax atomics for quantization.
// ---------------------------------------------------------------------------
#define AT_TS 128
#define AT_HALO 132
#define AT_ROWH 70            // halves per row stride (140 B -> conflict-free half2)
#define ATT_SMEM (AT_HALO * AT_ROWH * 2)   // 18480 B

__global__ void __launch_bounds__(256) attn_kernel(
    const float* __restrict__ bk, const float* __restrict__ bv)
{
    extern __shared__ __half smh[];

    const int by = blockIdx.y;
    const int b  = by / Hq;
    const int h  = by % Hq;
    const int s0 = blockIdx.x * AT_TS;

    const size_t basep = ((size_t)b * Sq) * Dq + h * DHq;
    const int tid = threadIdx.x;
    const int si  = tid >> 1;          // position within tile
    const int hh  = tid & 1;           // dim half

    // ---- stage K (fp16) ----
    {
        const float* Kg = g_K + basep;
        const float* bsrc = bk + h * DHq;
        for (int idx = tid; idx < AT_HALO * 32; idx += 256) {
            const int r = idx >> 5;
            const int c2 = (idx & 31) * 2;
            const int gs = s0 - 2 + r;
            float2 v = (gs >= 0 && gs < Sq)
                       ? *(const float2*)(Kg + (size_t)gs * Dq + c2)
                       : *(const float2*)(bsrc + c2);
            *(__half2*)&smh[r * AT_ROWH + c2] = __float22half2_rn(v);
        }
    }
    __syncthreads();

    const float* qrow = g_Q + ((size_t)b * Sq + s0 + si) * Dq + h * DHq + hh * 32;
    float2 qv[16];
    #pragma unroll
    for (int d2 = 0; d2 < 16; d2++) qv[d2] = *(const float2*)(qrow + 2 * d2);

    float sc[5];
    #pragma unroll
    for (int i = 0; i < 5; i++) {
        const __half2* krow = (const __half2*)&smh[(si + i) * AT_ROWH + hh * 32];
        float s = 0.f;
        #pragma unroll
        for (int d2 = 0; d2 < 16; d2++) {
            const float2 kf = __half22float2(krow[d2]);
            s += qv[d2].x * kf.x + qv[d2].y * kf.y;
        }
        sc[i] = s;
    }
    #pragma unroll
    for (int i = 0; i < 5; i++)
        sc[i] += __shfl_xor_sync(0xFFFFFFFFu, sc[i], 1);

    float mx = sc[0];
    #pragma unroll
    for (int i = 1; i < 5; i++) mx = fmaxf(mx, sc[i]);
    float p[5], sum = 0.f;
    #pragma unroll
    for (int i = 0; i < 5; i++) {
        p[i] = __expf((sc[i] - mx) * 0.125f);
        sum += p[i];
    }
    const float inv = 1.f / sum;
    #pragma unroll
    for (int i = 0; i < 5; i++) p[i] *= inv;

    // ---- stage V (reuse smem) ----
    __syncthreads();
    {
        const float* Vg = g_V + basep;
        const float* bsrc = bv + h * DHq;
        for (int idx = tid; idx < AT_HALO * 32; idx += 256) {
            const int r = idx >> 5;
            const int c2 = (idx & 31) * 2;
            const int gs = s0 - 2 + r;
            float2 v = (gs >= 0 && gs < Sq)
                       ? *(const float2*)(Vg + (size_t)gs * Dq + c2)
                       : *(const float2*)(bsrc + c2);
            *(__half2*)&smh[r * AT_ROWH + c2] = __float22half2_rn(v);
        }
    }
    __syncthreads();

    float2 o2[16];
    #pragma unroll
    for (int d2 = 0; d2 < 16; d2++) { o2[d2].x = 0.f; o2[d2].y = 0.f; }
    #pragma unroll
    for (int i = 0; i < 5; i++) {
        const __half2* vrow = (const __half2*)&smh[(si + i) * AT_ROWH + hh * 32];
        const float pi = p[i];
        #pragma unroll
        for (int d2 = 0; d2 < 16; d2++) {
            const float2 vf = __half22float2(vrow[d2]);
            o2[d2].x += pi * vf.x;
            o2[d2].y += pi * vf.y;
        }
    }

    const int row = b * Sq + s0 + si;
    float* orow = g_att + (size_t)row * Dq + h * DHq + hh * 32;
    float amx = 0.f;
    #pragma unroll
    for (int d2 = 0; d2 < 16; d2++) {
        *(float2*)(orow + 2 * d2) = o2[d2];
        amx = fmaxf(amx, fmaxf(fabsf(o2[d2].x), fabsf(o2[d2].y)));
    }
    atomicMax(&g_amax[row], __float_as_uint(amx));
}

// ---------------------------------------------------------------------------
// LayerNorm over last dim (768)
// ---------------------------------------------------------------------------
__global__ void __launch_bounds__(256) ln_kernel(
    const float* __restrict__ gamma, const float* __restrict__ beta,
    float* __restrict__ outp)
{
    const int row = blockIdx.x;
    const float* y = g_Y + (size_t)row * Dq;
    const int tid = threadIdx.x;

    float v[3];
    float s = 0.f, ss = 0.f;
    #pragma unroll
    for (int j = 0; j < 3; j++) {
        v[j] = y[tid + j * 256];
        s  += v[j];
        ss += v[j] * v[j];
    }
    #pragma unroll
    for (int o = 16; o > 0; o >>= 1) {
        s  += __shfl_xor_sync(0xFFFFFFFFu, s,  o);
        ss += __shfl_xor_sync(0xFFFFFFFFu, ss, o);
    }
    __shared__ float rs[8], rss[8];
    const int w = tid >> 5;
    if ((tid & 31) == 0) { rs[w] = s; rss[w] = ss; }
    __syncthreads();
    s = 0.f; ss = 0.f;
    #pragma unroll
    for (int i = 0; i < 8; i++) { s += rs[i]; ss += rss[i]; }

    const float mu   = s * (1.f / 768.f);
    const float var  = ss * (1.f / 768.f) - mu * mu;
    const float rstd = rsqrtf(var + 1e-5f);

    #pragma unroll
    for (int j = 0; j < 3; j++) {
        const int c = tid + j * 256;
        outp[(size_t)row * Dq + c] = (v[j] - mu) * rstd * gamma[c] + beta[c];
    }
}

// ---------------------------------------------------------------------------
// Launch
// ---------------------------------------------------------------------------
extern "C" void kernel_launch(void* const* d_in, const int* in_sizes, int n_in,
                              void* d_out, int out_size)
{
    const float* x     = (const float*)d_in[0];
    const float* Wq    = (const float*)d_in[1];
    const float* bq    = (const float*)d_in[2];
    const float* Wk    = (const float*)d_in[3];
    const float* bk    = (const float*)d_in[4];
    const float* Wv    = (const float*)d_in[5];
    const float* bv    = (const float*)d_in[6];
    const float* Wo    = (const float*)d_in[7];
    const float* bo    = (const float*)d_in[8];
    const float* gamma = (const float*)d_in[9];
    const float* beta  = (const float*)d_in[10];
    float* out = (float*)d_out;

    static int configured = 0;
    if (!configured) {
        cudaFuncSetAttribute(ig_gemm_kernel,
                             cudaFuncAttributeMaxDynamicSharedMemorySize, GEMM_SMEM);
        cudaFuncSetAttribute(attn_kernel,
                             cudaFuncAttributeMaxDynamicSharedMemorySize, ATT_SMEM);
        configured = 1;
    }

    int8_t *xq0, *xq1, *aq0, *aq1;
    float *xsc, *asc, *attp;
    cudaGetSymbolAddress((void**)&xq0, g_xq0);
    cudaGetSymbolAddress((void**)&xq1, g_xq1);
    cudaGetSymbolAddress((void**)&xsc, g_xsc);
    cudaGetSymbolAddress((void**)&aq0, g_aq0);
    cudaGetSymbolAddress((void**)&aq1, g_aq1);
    cudaGetSymbolAddress((void**)&asc, g_asc);
    cudaGetSymbolAddress((void**)&attp, g_att);

    // 0) quantize inputs + weights
    quant_rows_kernel<<<Mq, 256>>>(x, xq0, xq1, xsc);
    wmax_zero_kernel<<<12, 256>>>();
    wmax_kernel<<<dim3(3, 8, 4), 256>>>(Wq, Wk, Wv, Wo);
    wquant_kernel<<<dim3(24, 24, 4), 256>>>(Wq, Wk, Wv, Wo);
    zero_amax_kernel<<<Mq / 256, 256>>>();

    // 1) QKV projections (N = 2304 over 18 tiles, M over 512 tiles of 64)
    ig_gemm_kernel<<<dim3(18, Mq / BM), 256, GEMM_SMEM>>>(
        xq0, xq1, xsc, bq, bk, bv, nullptr, 0, 0);

    // 2) Banded local attention -> g_att fp32 + fused absmax
    attn_kernel<<<dim3(Sq / AT_TS, Bq * Hq), 256, ATT_SMEM>>>(bk, bv);

    // 3) quantize att (elementwise, absmax precomputed), then O projection
    quant_att_kernel<<<Mq, 256>>>(attp, aq0, aq1, asc);
    ig_gemm_kernel<<<dim3(6, Mq / BM), 256, GEMM_SMEM>>>(
        aq0, aq1, asc, bo, nullptr, nullptr, x, 3 * Dq, 1);

    // 4) LayerNorm -> d_out
    ln_kernel<<<Mq, 256>>>(gamma, beta, out);
}

// round 8
// speedup vs baseline: 1.8384x; 1.0903x over previous
#include <cuda_runtime.h>
#include <cuda_fp16.h>
#include <cstdint>

// Problem constants
#define Bq 8
#define Sq 4096
#define Dq 768
#define Hq 12
#define DHq 64
#define Mq (Bq * Sq)          // 32768 rows

// int8 GEMM tiling (mma.sync m16n8k32 s8 -> s32)
#define BM 64
#define BN 128
#define BK 64                 // int8 K elements per chunk
#define NCHUNK 12             // 768/64
// Swizzled 64B rows, no padding. seg' = seg ^ ((row>>1)&3), 16B segments.
#define A0_OFF 0
#define A1_OFF 4096
#define B0_OFF 8192
#define B1_OFF 16384
#define STAGE_B 24576
#define NSTAGE 3
#define GEMM_SMEM (NSTAGE * STAGE_B)   // 73728 -> 2 CTAs/SM

#define QMAX 16256.0f         // 127*128

// ---------------------------------------------------------------------------
// Scratch (device globals)
// ---------------------------------------------------------------------------
__device__ float g_Q[(size_t)Mq * Dq];
__device__ float g_K[(size_t)Mq * Dq];
__device__ float g_V[(size_t)Mq * Dq];
__device__ float g_Y[(size_t)Mq * Dq];
__device__ int8_t g_xq0[(size_t)Mq * Dq];
__device__ int8_t g_xq1[(size_t)Mq * Dq];
__device__ float  g_xsc[Mq];
__device__ int8_t g_aq0[(size_t)Mq * Dq];
__device__ int8_t g_aq1[(size_t)Mq * Dq];
__device__ float  g_asc[Mq];      // att row scale (amax/QMAX)
__device__ float  g_ainv[Mq];     // QMAX/amax
__device__ unsigned int g_vmax[Mq];
__device__ float  g_bvmax;
__device__ int8_t g_wq0[(size_t)4 * Dq * Dq];   // transposed [n][k]; rows: Wq|Wk|Wv|Wo
__device__ int8_t g_wq1[(size_t)4 * Dq * Dq];
__device__ float  g_wsc[4 * Dq];
__device__ unsigned int g_wmax[4 * Dq];

// ---------------------------------------------------------------------------
// PTX helpers
// ---------------------------------------------------------------------------
__device__ __forceinline__ uint32_t smem_u32(const void* p) {
    uint32_t a;
    asm("{ .reg .u64 t; cvta.to.shared.u64 t, %1; cvt.u32.u64 %0, t; }" : "=r"(a) : "l"(p));
    return a;
}
__device__ __forceinline__ void cp16(uint32_t dst, const void* src) {
    asm volatile("cp.async.cg.shared.global [%0], [%1], 16;" :: "r"(dst), "l"(src) : "memory");
}
__device__ __forceinline__ void cp_commit() { asm volatile("cp.async.commit_group;" ::: "memory"); }
__device__ __forceinline__ void cp_wait1()  { asm volatile("cp.async.wait_group 1;" ::: "memory"); }
__device__ __forceinline__ void cp_wait0()  { asm volatile("cp.async.wait_group 0;" ::: "memory"); }

__device__ __forceinline__ void ldsm_x4(uint32_t (&r)[4], uint32_t addr) {
    asm volatile("ldmatrix.sync.aligned.m8n8.x4.shared.b16 {%0,%1,%2,%3}, [%4];"
                 : "=r"(r[0]), "=r"(r[1]), "=r"(r[2]), "=r"(r[3]) : "r"(addr));
}
// D += A(s8 m16k32) * B(s8 n8k32), s32 accumulate
__device__ __forceinline__ void imma(int (&d)[4], const uint32_t (&a)[4],
                                     uint32_t b0, uint32_t b1) {
    asm volatile("mma.sync.aligned.m16n8k32.row.col.s32.s8.s8.s32 "
                 "{%0,%1,%2,%3}, {%4,%5,%6,%7}, {%8,%9}, {%0,%1,%2,%3};"
                 : "+r"(d[0]), "+r"(d[1]), "+r"(d[2]), "+r"(d[3])
                 : "r"(a[0]), "r"(a[1]), "r"(a[2]), "r"(a[3]), "r"(b0), "r"(b1));
}

// ---------------------------------------------------------------------------
// Row quantizer (with block reduce): per-row absmax -> 2-digit int8
// ---------------------------------------------------------------------------
__global__ void __launch_bounds__(256) quant_rows_kernel(
    const float* __restrict__ src, int8_t* __restrict__ q0,
    int8_t* __restrict__ q1, float* __restrict__ scl)
{
    const int row = blockIdx.x;
    const int tid = threadIdx.x;
    const float* s = src + (size_t)row * Dq;

    float v[3], mx = 0.f;
    #pragma unroll
    for (int j = 0; j < 3; j++) {
        v[j] = s[tid + j * 256];
        mx = fmaxf(mx, fabsf(v[j]));
    }
    #pragma unroll
    for (int o = 16; o > 0; o >>= 1)
        mx = fmaxf(mx, __shfl_xor_sync(0xFFFFFFFFu, mx, o));
    __shared__ float rm[8];
    if ((tid & 31) == 0) rm[tid >> 5] = mx;
    __syncthreads();
    mx = fmaxf(fmaxf(fmaxf(rm[0], rm[1]), fmaxf(rm[2], rm[3])),
               fmaxf(fmaxf(rm[4], rm[5]), fmaxf(rm[6], rm[7])));

    const float inv = (mx > 0.f) ? (QMAX / mx) : 0.f;
    if (tid == 0) scl[row] = (mx > 0.f) ? (mx / QMAX) : 0.f;

    #pragma unroll
    for (int j = 0; j < 3; j++) {
        const int c = tid + j * 256;
        const int n = __float2int_rn(v[j] * inv);
        const int a0 = (n + 64) >> 7;
        const int a1 = n - (a0 << 7);
        q0[(size_t)row * Dq + c] = (int8_t)a0;
        q1[(size_t)row * Dq + c] = (int8_t)a1;
    }
}

// ---------------------------------------------------------------------------
// Zero vmax; bv absmax; per-row att scale from vmax window
// ---------------------------------------------------------------------------
__global__ void __launch_bounds__(256) zero_vmax_kernel() {
    const int i = blockIdx.x * 256 + threadIdx.x;
    if (i < Mq) g_vmax[i] = 0u;
}
__global__ void __launch_bounds__(256) bvmax_kernel(const float* __restrict__ bv) {
    const int tid = threadIdx.x;
    float mx = fmaxf(fmaxf(fabsf(bv[tid]), fabsf(bv[tid + 256])), fabsf(bv[tid + 512]));
    #pragma unroll
    for (int o = 16; o > 0; o >>= 1)
        mx = fmaxf(mx, __shfl_xor_sync(0xFFFFFFFFu, mx, o));
    __shared__ float rm[8];
    if ((tid & 31) == 0) rm[tid >> 5] = mx;
    __syncthreads();
    if (tid == 0) {
        mx = fmaxf(fmaxf(fmaxf(rm[0], rm[1]), fmaxf(rm[2], rm[3])),
                   fmaxf(fmaxf(rm[4], rm[5]), fmaxf(rm[6], rm[7])));
        g_bvmax = mx;
    }
}
__global__ void __launch_bounds__(256) vscale_kernel() {
    const int row = blockIdx.x * 256 + threadIdx.x;
    const int b = row >> 12;          // /Sq
    const int s = row & (Sq - 1);
    float amax = g_bvmax;
    #pragma unroll
    for (int i = -2; i <= 2; i++) {
        const int ss = s + i;
        if (ss >= 0 && ss < Sq)
            amax = fmaxf(amax, __uint_as_float(g_vmax[(b << 12) + ss]));
    }
    if (amax <= 0.f) amax = 1e-20f;
    g_asc[row]  = amax / QMAX;
    g_ainv[row] = QMAX / amax;
}

// ---------------------------------------------------------------------------
// Weight absmax per output column (atomicMax on positive float bits)
// ---------------------------------------------------------------------------
__global__ void __launch_bounds__(256) wmax_zero_kernel() {
    const int i = blockIdx.x * 256 + threadIdx.x;
    if (i < 4 * Dq) g_wmax[i] = 0u;
}
__global__ void __launch_bounds__(256) wmax_kernel(
    const float* __restrict__ Wq, const float* __restrict__ Wk,
    const float* __restrict__ Wv, const float* __restrict__ Wo)
{
    const int w = blockIdx.z;
    const float* W = (w == 0) ? Wq : (w == 1) ? Wk : (w == 2) ? Wv : Wo;
    const int n = blockIdx.x * 256 + threadIdx.x;
    const int k0 = blockIdx.y * 96;
    float mx = 0.f;
    for (int j = 0; j < 96; j++)
        mx = fmaxf(mx, fabsf(W[(size_t)(k0 + j) * Dq + n]));
    atomicMax(&g_wmax[w * Dq + n], __float_as_uint(mx));
}

// ---------------------------------------------------------------------------
// Weight quantize + transpose: out[n][k] digits
// ---------------------------------------------------------------------------
__global__ void __launch_bounds__(256) wquant_kernel(
    const float* __restrict__ Wq, const float* __restrict__ Wk,
    const float* __restrict__ Wv, const float* __restrict__ Wo)
{
    __shared__ float t[32][33];
    const int w = blockIdx.z;
    const float* W = (w == 0) ? Wq : (w == 1) ? Wk : (w == 2) ? Wv : Wo;
    const int n0 = blockIdx.x * 32, k0 = blockIdx.y * 32;
    const int tx = threadIdx.x & 31, ty = threadIdx.x >> 5;

    #pragma unroll
    for (int i = 0; i < 4; i++)
        t[ty + i * 8][tx] = W[(size_t)(k0 + ty + i * 8) * Dq + n0 + tx];
    __syncthreads();
    #pragma unroll
    for (int i = 0; i < 4; i++) {
        const int n = n0 + ty + i * 8;
        const float mx = __uint_as_float(g_wmax[w * Dq + n]);
        const float inv = (mx > 0.f) ? (QMAX / mx) : 0.f;
        if (k0 == 0 && tx == 0)
            g_wsc[w * Dq + n] = (mx > 0.f) ? (mx / QMAX) : 0.f;
        const float val = t[tx][ty + i * 8];        // W[k0+tx][n]
        const int q = __float2int_rn(val * inv);
        const int a0 = (q + 64) >> 7;
        const int a1 = q - (a0 << 7);
        const size_t o = (size_t)(w * Dq + n) * Dq + k0 + tx;
        g_wq0[o] = (int8_t)a0;
        g_wq1[o] = (int8_t)a1;
    }
}

// ---------------------------------------------------------------------------
// int8 tensor-core GEMM (R7-proven): C[64 x 128] = A @ W^T, 3 IMMA products.
// mode 0: outputs Q|K|V (+bias) and V-row absmax atomics, grid (18, 512)
// mode 1: g_Y = C + bo + resid, grid (6, 512)
// ---------------------------------------------------------------------------
__global__ void __launch_bounds__(256, 2) ig_gemm_kernel(
    const int8_t* __restrict__ Aq0, const int8_t* __restrict__ Aq1,
    const float* __restrict__ Asc,
    const float* __restrict__ bias_a, const float* __restrict__ bias_b,
    const float* __restrict__ bias_c, const float* __restrict__ resid,
    int wbase, int mode)
{
    extern __shared__ __align__(128) char smem_raw[];
    const uint32_t base = smem_u32(smem_raw);

    const int tid  = threadIdx.x;
    const int wid  = tid >> 5;
    const int lane = tid & 31;
    const int m0 = blockIdx.y * BM;
    const int bx = blockIdx.x;
    const int nrow0 = wbase + bx * BN;

    const int wm0 = (wid & 1) * 32;          // 2 warps in M
    const int wn0 = (wid >> 1) * 32;         // 4 warps in N

    const int rA   = tid >> 2;
    const int sgA  = tid & 3;
    const uint32_t soA = (uint32_t)(rA * 64 + ((sgA ^ ((rA >> 1) & 3)) << 4));

    auto load_stage = [&](int c, int s) {
        const int k0 = c * BK;
        const uint32_t sb = base + (uint32_t)s * STAGE_B;
        cp16(sb + A0_OFF + soA, Aq0 + (size_t)(m0 + rA) * Dq + k0 + sgA * 16);
        cp16(sb + A1_OFF + soA, Aq1 + (size_t)(m0 + rA) * Dq + k0 + sgA * 16);
        #pragma unroll
        for (int half = 0; half < 2; half++) {
            const int u = tid + half * 256;
            const int rB = u >> 2, sgB = u & 3;
            const uint32_t soB = (uint32_t)(rB * 64 + ((sgB ^ ((rB >> 1) & 3)) << 4));
            cp16(sb + B0_OFF + soB, g_wq0 + (size_t)(nrow0 + rB) * Dq + k0 + sgB * 16);
            cp16(sb + B1_OFF + soB, g_wq1 + (size_t)(nrow0 + rB) * Dq + k0 + sgB * 16);
        }
        cp_commit();
    };

    int hi[2][4][4], mid[2][4][4];
    #pragma unroll
    for (int mi = 0; mi < 2; mi++)
        #pragma unroll
        for (int n8 = 0; n8 < 4; n8++)
            #pragma unroll
            for (int j = 0; j < 4; j++) { hi[mi][n8][j] = 0; mid[mi][n8][j] = 0; }

    const int lrow = (lane & 7) + ((lane >> 3) & 1) * 8;
    const int lkseg = (lane >> 4);

    load_stage(0, 0);
    load_stage(1, 1);

    for (int c = 0; c < NCHUNK; c++) {
        if (c + 1 < NCHUNK) cp_wait1();
        else                cp_wait0();
        __syncthreads();
        if (c + 2 < NCHUNK) load_stage(c + 2, (c + 2) % NSTAGE);

        const uint32_t sb = base + (uint32_t)(c % NSTAGE) * STAGE_B;
        const uint32_t sA0 = sb + A0_OFF, sA1 = sb + A1_OFF;
        const uint32_t sB0 = sb + B0_OFF, sB1 = sb + B1_OFF;

        #pragma unroll
        for (int ks = 0; ks < 2; ks++) {
            const int segk = ks * 2 + lkseg;
            uint32_t a0[2][4], a1[2][4];
            #pragma unroll
            for (int mi = 0; mi < 2; mi++) {
                const int row = wm0 + mi * 16 + lrow;
                const uint32_t ro = (uint32_t)(row * 64 + ((segk ^ ((row >> 1) & 3)) << 4));
                ldsm_x4(a0[mi], sA0 + ro);
                ldsm_x4(a1[mi], sA1 + ro);
            }
            #pragma unroll
            for (int g = 0; g < 2; g++) {
                uint32_t b0[4], b1[4];
                const int row = wn0 + g * 16 + lrow;
                const uint32_t ro = (uint32_t)(row * 64 + ((segk ^ ((row >> 1) & 3)) << 4));
                ldsm_x4(b0, sB0 + ro);
                ldsm_x4(b1, sB1 + ro);
                #pragma unroll
                for (int mi = 0; mi < 2; mi++) {
                    imma(hi[mi][g * 2 + 0], a0[mi], b0[0], b0[2]);
                    imma(hi[mi][g * 2 + 1], a0[mi], b0[1], b0[3]);
                    imma(mid[mi][g * 2 + 0], a0[mi], b1[0], b1[2]);
                    imma(mid[mi][g * 2 + 1], a0[mi], b1[1], b1[3]);
                    imma(mid[mi][g * 2 + 0], a1[mi], b0[0], b0[2]);
                    imma(mid[mi][g * 2 + 1], a1[mi], b0[1], b0[3]);
                }
            }
        }
    }

    // ---- epilogue ----
    float* outp;
    const float* bias;
    int n0in, sel = 0;
    if (mode == 0) {
        sel = bx / 6;
        n0in = (bx % 6) * BN;
        outp = (sel == 0) ? g_Q : (sel == 1) ? g_K : g_V;
        bias = (sel == 0) ? bias_a : (sel == 1) ? bias_b : bias_c;
    } else {
        n0in = bx * BN;
        outp = g_Y;
        bias = bias_a;
    }

    const int qr = lane >> 2;
    const int qc = (lane & 3) * 2;
    #pragma unroll
    for (int mi = 0; mi < 2; mi++) {
        #pragma unroll
        for (int half = 0; half < 2; half++) {
            const int m = m0 + wm0 + mi * 16 + qr + half * 8;
            const float sa128 = Asc[m] * 128.f;
            float lmax = 0.f;
            #pragma unroll
            for (int n8 = 0; n8 < 4; n8++) {
                const int nl = wn0 + n8 * 8 + qc;
                const float sb0 = g_wsc[nrow0 + nl] * sa128;
                const float sb1 = g_wsc[nrow0 + nl + 1] * sa128;
                const int n = n0in + nl;
                const size_t o = (size_t)m * Dq + n;
                const int t0 = hi[mi][n8][half * 2 + 0] * 128 + mid[mi][n8][half * 2 + 0];
                const int t1 = hi[mi][n8][half * 2 + 1] * 128 + mid[mi][n8][half * 2 + 1];
                float2 v;
                v.x = (float)t0 * sb0 + bias[n];
                v.y = (float)t1 * sb1 + bias[n + 1];
                if (mode == 1) {
                    v.x += resid[o];
                    v.y += resid[o + 1];
                }
                *(float2*)(outp + o) = v;
                lmax = fmaxf(lmax, fmaxf(fabsf(v.x), fabsf(v.y)));
            }
            if (mode == 0 && sel == 2) {
                // reduce over the 4 lanes sharing this row, one atomic per group
                lmax = fmaxf(lmax, __shfl_xor_sync(0xFFFFFFFFu, lmax, 1));
                lmax = fmaxf(lmax, __shfl_xor_sync(0xFFFFFFFFu, lmax, 2));
                if ((lane & 3) == 0)
                    atomicMax(&g_vmax[m], __float_as_uint(lmax));
            }
        }
    }
}

// ---------------------------------------------------------------------------
// Banded attention: 2 threads per position, fp16 K/V staging, writes int8
// digits directly using precomputed per-row scale bound (g_ainv).
// ---------------------------------------------------------------------------
#define AT_TS 128
#define AT_HALO 132
#define AT_ROWH 70            // halves per row stride (140 B -> conflict-free half2)
#define ATT_SMEM (AT_HALO * AT_ROWH * 2)   // 18480 B

__global__ void __launch_bounds__(256) attn_kernel(
    const float* __restrict__ bk, const float* __restrict__ bv,
    int8_t* __restrict__ aq0, int8_t* __restrict__ aq1)
{
    extern __shared__ __half smh[];

    const int by = blockIdx.y;
    const int b  = by / Hq;
    const int h  = by % Hq;
    const int s0 = blockIdx.x * AT_TS;

    const size_t basep = ((size_t)b * Sq) * Dq + h * DHq;
    const int tid = threadIdx.x;
    const int si  = tid >> 1;          // position within tile
    const int hh  = tid & 1;           // dim half

    // ---- stage K (fp16) ----
    {
        const float* Kg = g_K + basep;
        const float* bsrc = bk + h * DHq;
        for (int idx = tid; idx < AT_HALO * 32; idx += 256) {
            const int r = idx >> 5;
            const int c2 = (idx & 31) * 2;
            const int gs = s0 - 2 + r;
            float2 v = (gs >= 0 && gs < Sq)
                       ? *(const float2*)(Kg + (size_t)gs * Dq + c2)
                       : *(const float2*)(bsrc + c2);
            *(__half2*)&smh[r * AT_ROWH + c2] = __float22half2_rn(v);
        }
    }
    __syncthreads();

    const float* qrow = g_Q + ((size_t)b * Sq + s0 + si) * Dq + h * DHq + hh * 32;
    float2 qv[16];
    #pragma unroll
    for (int d2 = 0; d2 < 16; d2++) qv[d2] = *(const float2*)(qrow + 2 * d2);

    float sc[5];
    #pragma unroll
    for (int i = 0; i < 5; i++) {
        const __half2* krow = (const __half2*)&smh[(si + i) * AT_ROWH + hh * 32];
        float s = 0.f;
        #pragma unroll
        for (int d2 = 0; d2 < 16; d2++) {
            const float2 kf = __half22float2(krow[d2]);
            s += qv[d2].x * kf.x + qv[d2].y * kf.y;
        }
        sc[i] = s;
    }
    #pragma unroll
    for (int i = 0; i < 5; i++)
        sc[i] += __shfl_xor_sync(0xFFFFFFFFu, sc[i], 1);

    float mx = sc[0];
    #pragma unroll
    for (int i = 1; i < 5; i++) mx = fmaxf(mx, sc[i]);
    float p[5], sum = 0.f;
    #pragma unroll
    for (int i = 0; i < 5; i++) {
        p[i] = __expf((sc[i] - mx) * 0.125f);
        sum += p[i];
    }
    const float inv = 1.f / sum;
    #pragma unroll
    for (int i = 0; i < 5; i++) p[i] *= inv;

    // ---- stage V (reuse smem) ----
    __syncthreads();
    {
        const float* Vg = g_V + basep;
        const float* bsrc = bv + h * DHq;
        for (int idx = tid; idx < AT_HALO * 32; idx += 256) {
            const int r = idx >> 5;
            const int c2 = (idx & 31) * 2;
            const int gs = s0 - 2 + r;
            float2 v = (gs >= 0 && gs < Sq)
                       ? *(const float2*)(Vg + (size_t)gs * Dq + c2)
                       : *(const float2*)(bsrc + c2);
            *(__half2*)&smh[r * AT_ROWH + c2] = __float22half2_rn(v);
        }
    }
    __syncthreads();

    float2 o2[16];
    #pragma unroll
    for (int d2 = 0; d2 < 16; d2++) { o2[d2].x = 0.f; o2[d2].y = 0.f; }
    #pragma unroll
    for (int i = 0; i < 5; i++) {
        const __half2* vrow = (const __half2*)&smh[(si + i) * AT_ROWH + hh * 32];
        const float pi = p[i];
        #pragma unroll
        for (int d2 = 0; d2 < 16; d2++) {
            const float2 vf = __half22float2(vrow[d2]);
            o2[d2].x += pi * vf.x;
            o2[d2].y += pi * vf.y;
        }
    }

    // ---- quantize in-register with precomputed row scale, write digits ----
    const int row = b * Sq + s0 + si;
    const float qinv = g_ainv[row];
    uint32_t p0[8], p1[8];
    #pragma unroll
    for (int d2 = 0; d2 < 8; d2++) {
        uint32_t w0 = 0, w1 = 0;
        #pragma unroll
        for (int j = 0; j < 2; j++) {
            const float2 o = o2[d2 * 2 + j];
            const int nx = __float2int_rn(o.x * qinv);
            const int ax0 = (nx + 64) >> 7;
            const int ax1 = nx - (ax0 << 7);
            const int ny = __float2int_rn(o.y * qinv);
            const int ay0 = (ny + 64) >> 7;
            const int ay1 = ny - (ay0 << 7);
            w0 |= ((uint32_t)(ax0 & 255) << (j * 16)) | ((uint32_t)(ay0 & 255) << (j * 16 + 8));
            w1 |= ((uint32_t)(ax1 & 255) << (j * 16)) | ((uint32_t)(ay1 & 255) << (j * 16 + 8));
        }
        p0[d2] = w0;
        p1[d2] = w1;
    }
    const size_t obase = (size_t)row * Dq + h * DHq + hh * 32;
    *(uint4*)(aq0 + obase)      = make_uint4(p0[0], p0[1], p0[2], p0[3]);
    *(uint4*)(aq0 + obase + 16) = make_uint4(p0[4], p0[5], p0[6], p0[7]);
    *(uint4*)(aq1 + obase)      = make_uint4(p1[0], p1[1], p1[2], p1[3]);
    *(uint4*)(aq1 + obase + 16) = make_uint4(p1[4], p1[5], p1[6], p1[7]);
}

// ---------------------------------------------------------------------------
// LayerNorm over last dim (768), float4 loads, 192 threads
// ---------------------------------------------------------------------------
__global__ void __launch_bounds__(192) ln_kernel(
    const float* __restrict__ gamma, const float* __restrict__ beta,
    float* __restrict__ outp)
{
    const int row = blockIdx.x;
    const float* y = g_Y + (size_t)row * Dq;
    const int tid = threadIdx.x;

    float4 v = *(const float4*)(y + tid * 4);
    float s  = v.x + v.y + v.z + v.w;
    float ss = v.x * v.x + v.y * v.y + v.z * v.z + v.w * v.w;
    #pragma unroll
    for (int o = 16; o > 0; o >>= 1) {
        s  += __shfl_xor_sync(0xFFFFFFFFu, s,  o);
        ss += __shfl_xor_sync(0xFFFFFFFFu, ss, o);
    }
    __shared__ float rs[6], rss[6];
    const int w = tid >> 5;
    if ((tid & 31) == 0) { rs[w] = s; rss[w] = ss; }
    __syncthreads();
    s  = rs[0] + rs[1] + rs[2] + rs[3] + rs[4] + rs[5];
    ss = rss[0] + rss[1] + rss[2] + rss[3] + rss[4] + rss[5];

    const float mu   = s * (1.f / 768.f);
    const float var  = ss * (1.f / 768.f) - mu * mu;
    const float rstd = rsqrtf(var + 1e-5f);

    const float4 g = *(const float4*)(gamma + tid * 4);
    const float4 be = *(const float4*)(beta + tid * 4);
    float4 o;
    o.x = (v.x - mu) * rstd * g.x + be.x;
    o.y = (v.y - mu) * rstd * g.y + be.y;
    o.z = (v.z - mu) * rstd * g.z + be.z;
    o.w = (v.w - mu) * rstd * g.w + be.w;
    *(float4*)(outp + (size_t)row * Dq + tid * 4) = o;
}

// ---------------------------------------------------------------------------
// Launch
// ---------------------------------------------------------------------------
extern "C" void kernel_launch(void* const* d_in, const int* in_sizes, int n_in,
                              void* d_out, int out_size)
{
    const float* x     = (const float*)d_in[0];
    const float* Wq    = (const float*)d_in[1];
    const float* bq    = (const float*)d_in[2];
    const float* Wk    = (const float*)d_in[3];
    const float* bk    = (const float*)d_in[4];
    const float* Wv    = (const float*)d_in[5];
    const float* bv    = (const float*)d_in[6];
    const float* Wo    = (const float*)d_in[7];
    const float* bo    = (const float*)d_in[8];
    const float* gamma = (const float*)d_in[9];
    const float* beta  = (const float*)d_in[10];
    float* out = (float*)d_out;

    static int configured = 0;
    if (!configured) {
        cudaFuncSetAttribute(ig_gemm_kernel,
                             cudaFuncAttributeMaxDynamicSharedMemorySize, GEMM_SMEM);
        cudaFuncSetAttribute(attn_kernel,
                             cudaFuncAttributeMaxDynamicSharedMemorySize, ATT_SMEM);
        configured = 1;
    }

    int8_t *xq0, *xq1, *aq0, *aq1;
    float *xsc, *asc;
    cudaGetSymbolAddress((void**)&xq0, g_xq0);
    cudaGetSymbolAddress((void**)&xq1, g_xq1);
    cudaGetSymbolAddress((void**)&xsc, g_xsc);
    cudaGetSymbolAddress((void**)&aq0, g_aq0);
    cudaGetSymbolAddress((void**)&aq1, g_aq1);
    cudaGetSymbolAddress((void**)&asc, g_asc);

    // 0) quantize inputs + weights; prep vmax machinery
    zero_vmax_kernel<<<Mq / 256, 256>>>();
    bvmax_kernel<<<1, 256>>>(bv);
    quant_rows_kernel<<<Mq, 256>>>(x, xq0, xq1, xsc);
    wmax_zero_kernel<<<12, 256>>>();
    wmax_kernel<<<dim3(3, 8, 4), 256>>>(Wq, Wk, Wv, Wo);
    wquant_kernel<<<dim3(24, 24, 4), 256>>>(Wq, Wk, Wv, Wo);

    // 1) QKV projections (+ V row absmax atomics)
    ig_gemm_kernel<<<dim3(18, Mq / BM), 256, GEMM_SMEM>>>(
        xq0, xq1, xsc, bq, bk, bv, nullptr, 0, 0);

    // 2) per-row att scale bound from V window, then fused attention+quant
    vscale_kernel<<<Mq / 256, 256>>>();
    attn_kernel<<<dim3(Sq / AT_TS, Bq * Hq), 256, ATT_SMEM>>>(bk, bv, aq0, aq1);

    // 3) O projection + bias + residual -> g_Y
    ig_gemm_kernel<<<dim3(6, Mq / BM), 256, GEMM_SMEM>>>(
        aq0, aq1, asc, bo, nullptr, nullptr, x, 3 * Dq, 1);

    // 4) LayerNorm -> d_out
    ln_kernel<<<Mq, 192>>>(gamma, beta, out);
}

// round 9
// speedup vs baseline: 1.8964x; 1.0315x over previous
#include <cuda_runtime.h>
#include <cuda_fp16.h>
#include <cstdint>

// Problem constants
#define Bq 8
#define Sq 4096
#define Dq 768
#define Hq 12
#define DHq 64
#define Mq (Bq * Sq)          // 32768 rows

// int8 GEMM tiling (mma.sync m16n8k32 s8 -> s32)
#define BM 64
#define BN 128
#define BK 64                 // int8 K elements per chunk
#define NCHUNK 12             // 768/64
// Swizzled 64B rows, no padding. seg' = seg ^ ((row>>1)&3), 16B segments.
#define A0_OFF 0
#define A1_OFF 4096
#define B0_OFF 8192
#define B1_OFF 16384
#define STAGE_B 24576
#define NSTAGE 3
#define GEMM_SMEM (NSTAGE * STAGE_B)   // 73728 -> 2 CTAs/SM

#define QMAX 16256.0f         // 127*128

// ---------------------------------------------------------------------------
// Scratch (device globals)
// ---------------------------------------------------------------------------
__device__ __half g_Q[(size_t)Mq * Dq];
__device__ __half g_K[(size_t)Mq * Dq];
__device__ __half g_V[(size_t)Mq * Dq];
__device__ float  g_Y[(size_t)Mq * Dq];
__device__ int8_t g_xq0[(size_t)Mq * Dq];
__device__ int8_t g_xq1[(size_t)Mq * Dq];
__device__ float  g_xsc[Mq];
__device__ int8_t g_aq0[(size_t)Mq * Dq];
__device__ int8_t g_aq1[(size_t)Mq * Dq];
__device__ float  g_asc[Mq];      // att row scale (amax/QMAX)
__device__ float  g_ainv[Mq];     // QMAX/amax
__device__ unsigned int g_vmax[Mq];
__device__ float  g_bvmax;
__device__ int8_t g_wq0[(size_t)4 * Dq * Dq];   // transposed [n][k]; rows: Wq|Wk|Wv|Wo
__device__ int8_t g_wq1[(size_t)4 * Dq * Dq];
__device__ float  g_wsc[4 * Dq];
__device__ unsigned int g_wmax[4 * Dq];

// ---------------------------------------------------------------------------
// PTX helpers
// ---------------------------------------------------------------------------
__device__ __forceinline__ uint32_t smem_u32(const void* p) {
    uint32_t a;
    asm("{ .reg .u64 t; cvta.to.shared.u64 t, %1; cvt.u32.u64 %0, t; }" : "=r"(a) : "l"(p));
    return a;
}
__device__ __forceinline__ void cp16(uint32_t dst, const void* src) {
    asm volatile("cp.async.cg.shared.global [%0], [%1], 16;" :: "r"(dst), "l"(src) : "memory");
}
__device__ __forceinline__ void cp_commit() { asm volatile("cp.async.commit_group;" ::: "memory"); }
__device__ __forceinline__ void cp_wait1()  { asm volatile("cp.async.wait_group 1;" ::: "memory"); }
__device__ __forceinline__ void cp_wait0()  { asm volatile("cp.async.wait_group 0;" ::: "memory"); }

__device__ __forceinline__ void ldsm_x4(uint32_t (&r)[4], uint32_t addr) {
    asm volatile("ldmatrix.sync.aligned.m8n8.x4.shared.b16 {%0,%1,%2,%3}, [%4];"
                 : "=r"(r[0]), "=r"(r[1]), "=r"(r[2]), "=r"(r[3]) : "r"(addr));
}
// D += A(s8 m16k32) * B(s8 n8k32), s32 accumulate
__device__ __forceinline__ void imma(int (&d)[4], const uint32_t (&a)[4],
                                     uint32_t b0, uint32_t b1) {
    asm volatile("mma.sync.aligned.m16n8k32.row.col.s32.s8.s8.s32 "
                 "{%0,%1,%2,%3}, {%4,%5,%6,%7}, {%8,%9}, {%0,%1,%2,%3};"
                 : "+r"(d[0]), "+r"(d[1]), "+r"(d[2]), "+r"(d[3])
                 : "r"(a[0]), "r"(a[1]), "r"(a[2]), "r"(a[3]), "r"(b0), "r"(b1));
}

// ---------------------------------------------------------------------------
// Row quantizer (float4, 192 threads): per-row absmax -> 2-digit int8
// ---------------------------------------------------------------------------
__global__ void __launch_bounds__(192) quant_rows_kernel(
    const float* __restrict__ src, int8_t* __restrict__ q0,
    int8_t* __restrict__ q1, float* __restrict__ scl)
{
    const int row = blockIdx.x;
    const int tid = threadIdx.x;
    const float4 v = *(const float4*)(src + (size_t)row * Dq + tid * 4);

    float mx = fmaxf(fmaxf(fabsf(v.x), fabsf(v.y)), fmaxf(fabsf(v.z), fabsf(v.w)));
    #pragma unroll
    for (int o = 16; o > 0; o >>= 1)
        mx = fmaxf(mx, __shfl_xor_sync(0xFFFFFFFFu, mx, o));
    __shared__ float rm[6];
    if ((tid & 31) == 0) rm[tid >> 5] = mx;
    __syncthreads();
    mx = fmaxf(fmaxf(fmaxf(rm[0], rm[1]), fmaxf(rm[2], rm[3])), fmaxf(rm[4], rm[5]));

    const float inv = (mx > 0.f) ? (QMAX / mx) : 0.f;
    if (tid == 0) scl[row] = (mx > 0.f) ? (mx / QMAX) : 0.f;

    const float f[4] = {v.x, v.y, v.z, v.w};
    uint32_t w0 = 0, w1 = 0;
    #pragma unroll
    for (int j = 0; j < 4; j++) {
        const int n = __float2int_rn(f[j] * inv);
        const int a0 = (n + 64) >> 7;
        const int a1 = n - (a0 << 7);
        w0 |= (uint32_t)(a0 & 255) << (j * 8);
        w1 |= (uint32_t)(a1 & 255) << (j * 8);
    }
    *(uint32_t*)(q0 + (size_t)row * Dq + tid * 4) = w0;
    *(uint32_t*)(q1 + (size_t)row * Dq + tid * 4) = w1;
}

// ---------------------------------------------------------------------------
// Merged init: zero vmax + wmax; block Mq/256 handles bvmax
// ---------------------------------------------------------------------------
__global__ void __launch_bounds__(256) init_kernel(const float* __restrict__ bv) {
    const int blk = blockIdx.x;
    const int tid = threadIdx.x;
    const int i = blk * 256 + tid;
    if (i < Mq) g_vmax[i] = 0u;
    if (i < 4 * Dq) g_wmax[i] = 0u;
    if (blk == gridDim.x - 1) {   // last block also reduces |bv|
        float mx = fmaxf(fmaxf(fabsf(bv[tid]), fabsf(bv[tid + 256])), fabsf(bv[tid + 512]));
        #pragma unroll
        for (int o = 16; o > 0; o >>= 1)
            mx = fmaxf(mx, __shfl_xor_sync(0xFFFFFFFFu, mx, o));
        __shared__ float rm[8];
        if ((tid & 31) == 0) rm[tid >> 5] = mx;
        __syncthreads();
        if (tid == 0) {
            mx = fmaxf(fmaxf(fmaxf(rm[0], rm[1]), fmaxf(rm[2], rm[3])),
                       fmaxf(fmaxf(rm[4], rm[5]), fmaxf(rm[6], rm[7])));
            g_bvmax = mx;
        }
    }
}

__global__ void __launch_bounds__(256) vscale_kernel() {
    const int row = blockIdx.x * 256 + threadIdx.x;
    const int b = row >> 12;          // /Sq
    const int s = row & (Sq - 1);
    float amax = g_bvmax;
    #pragma unroll
    for (int i = -2; i <= 2; i++) {
        const int ss = s + i;
        if (ss >= 0 && ss < Sq)
            amax = fmaxf(amax, __uint_as_float(g_vmax[(b << 12) + ss]));
    }
    if (amax <= 0.f) amax = 1e-20f;
    g_asc[row]  = amax / QMAX;
    g_ainv[row] = QMAX / amax;
}

// ---------------------------------------------------------------------------
// Weight absmax per output column (atomicMax on positive float bits)
// ---------------------------------------------------------------------------
__global__ void __launch_bounds__(256) wmax_kernel(
    const float* __restrict__ Wq, const float* __restrict__ Wk,
    const float* __restrict__ Wv, const float* __restrict__ Wo)
{
    const int w = blockIdx.z;
    const float* W = (w == 0) ? Wq : (w == 1) ? Wk : (w == 2) ? Wv : Wo;
    const int n = blockIdx.x * 256 + threadIdx.x;
    const int k0 = blockIdx.y * 96;
    float mx = 0.f;
    for (int j = 0; j < 96; j++)
        mx = fmaxf(mx, fabsf(W[(size_t)(k0 + j) * Dq + n]));
    atomicMax(&g_wmax[w * Dq + n], __float_as_uint(mx));
}

// ---------------------------------------------------------------------------
// Weight quantize + transpose: out[n][k] digits
// ---------------------------------------------------------------------------
__global__ void __launch_bounds__(256) wquant_kernel(
    const float* __restrict__ Wq, const float* __restrict__ Wk,
    const float* __restrict__ Wv, const float* __restrict__ Wo)
{
    __shared__ float t[32][33];
    const int w = blockIdx.z;
    const float* W = (w == 0) ? Wq : (w == 1) ? Wk : (w == 2) ? Wv : Wo;
    const int n0 = blockIdx.x * 32, k0 = blockIdx.y * 32;
    const int tx = threadIdx.x & 31, ty = threadIdx.x >> 5;

    #pragma unroll
    for (int i = 0; i < 4; i++)
        t[ty + i * 8][tx] = W[(size_t)(k0 + ty + i * 8) * Dq + n0 + tx];
    __syncthreads();
    #pragma unroll
    for (int i = 0; i < 4; i++) {
        const int n = n0 + ty + i * 8;
        const float mx = __uint_as_float(g_wmax[w * Dq + n]);
        const float inv = (mx > 0.f) ? (QMAX / mx) : 0.f;
        if (k0 == 0 && tx == 0)
            g_wsc[w * Dq + n] = (mx > 0.f) ? (mx / QMAX) : 0.f;
        const float val = t[tx][ty + i * 8];        // W[k0+tx][n]
        const int q = __float2int_rn(val * inv);
        const int a0 = (q + 64) >> 7;
        const int a1 = q - (a0 << 7);
        const size_t o = (size_t)(w * Dq + n) * Dq + k0 + tx;
        g_wq0[o] = (int8_t)a0;
        g_wq1[o] = (int8_t)a1;
    }
}

// ---------------------------------------------------------------------------
// int8 tensor-core GEMM (R7-proven): C[64 x 128] = A @ W^T, 3 IMMA products.
// mode 0: outputs Q|K|V as fp16 (+bias) and V-row absmax atomics, grid (18, 512)
// mode 1: g_Y = C + bo + resid (fp32), grid (6, 512)
// ---------------------------------------------------------------------------
__global__ void __launch_bounds__(256, 2) ig_gemm_kernel(
    const int8_t* __restrict__ Aq0, const int8_t* __restrict__ Aq1,
    const float* __restrict__ Asc,
    const float* __restrict__ bias_a, const float* __restrict__ bias_b,
    const float* __restrict__ bias_c, const float* __restrict__ resid,
    int wbase, int mode)
{
    extern __shared__ __align__(128) char smem_raw[];
    const uint32_t base = smem_u32(smem_raw);

    const int tid  = threadIdx.x;
    const int wid  = tid >> 5;
    const int lane = tid & 31;
    const int m0 = blockIdx.y * BM;
    const int bx = blockIdx.x;
    const int nrow0 = wbase + bx * BN;

    const int wm0 = (wid & 1) * 32;          // 2 warps in M
    const int wn0 = (wid >> 1) * 32;         // 4 warps in N

    const int rA   = tid >> 2;
    const int sgA  = tid & 3;
    const uint32_t soA = (uint32_t)(rA * 64 + ((sgA ^ ((rA >> 1) & 3)) << 4));

    auto load_stage = [&](int c, int s) {
        const int k0 = c * BK;
        const uint32_t sb = base + (uint32_t)s * STAGE_B;
        cp16(sb + A0_OFF + soA, Aq0 + (size_t)(m0 + rA) * Dq + k0 + sgA * 16);
        cp16(sb + A1_OFF + soA, Aq1 + (size_t)(m0 + rA) * Dq + k0 + sgA * 16);
        #pragma unroll
        for (int half = 0; half < 2; half++) {
            const int u = tid + half * 256;
            const int rB = u >> 2, sgB = u & 3;
            const uint32_t soB = (uint32_t)(rB * 64 + ((sgB ^ ((rB >> 1) & 3)) << 4));
            cp16(sb + B0_OFF + soB, g_wq0 + (size_t)(nrow0 + rB) * Dq + k0 + sgB * 16);
            cp16(sb + B1_OFF + soB, g_wq1 + (size_t)(nrow0 + rB) * Dq + k0 + sgB * 16);
        }
        cp_commit();
    };

    int hi[2][4][4], mid[2][4][4];
    #pragma unroll
    for (int mi = 0; mi < 2; mi++)
        #pragma unroll
        for (int n8 = 0; n8 < 4; n8++)
            #pragma unroll
            for (int j = 0; j < 4; j++) { hi[mi][n8][j] = 0; mid[mi][n8][j] = 0; }

    const int lrow = (lane & 7) + ((lane >> 3) & 1) * 8;
    const int lkseg = (lane >> 4);

    load_stage(0, 0);
    load_stage(1, 1);

    for (int c = 0; c < NCHUNK; c++) {
        if (c + 1 < NCHUNK) cp_wait1();
        else                cp_wait0();
        __syncthreads();
        if (c + 2 < NCHUNK) load_stage(c + 2, (c + 2) % NSTAGE);

        const uint32_t sb = base + (uint32_t)(c % NSTAGE) * STAGE_B;
        const uint32_t sA0 = sb + A0_OFF, sA1 = sb + A1_OFF;
        const uint32_t sB0 = sb + B0_OFF, sB1 = sb + B1_OFF;

        #pragma unroll
        for (int ks = 0; ks < 2; ks++) {
            const int segk = ks * 2 + lkseg;
            uint32_t a0[2][4], a1[2][4];
            #pragma unroll
            for (int mi = 0; mi < 2; mi++) {
                const int row = wm0 + mi * 16 + lrow;
                const uint32_t ro = (uint32_t)(row * 64 + ((segk ^ ((row >> 1) & 3)) << 4));
                ldsm_x4(a0[mi], sA0 + ro);
                ldsm_x4(a1[mi], sA1 + ro);
            }
            #pragma unroll
            for (int g = 0; g < 2; g++) {
                uint32_t b0[4], b1[4];
                const int row = wn0 + g * 16 + lrow;
                const uint32_t ro = (uint32_t)(row * 64 + ((segk ^ ((row >> 1) & 3)) << 4));
                ldsm_x4(b0, sB0 + ro);
                ldsm_x4(b1, sB1 + ro);
                #pragma unroll
                for (int mi = 0; mi < 2; mi++) {
                    imma(hi[mi][g * 2 + 0], a0[mi], b0[0], b0[2]);
                    imma(hi[mi][g * 2 + 1], a0[mi], b0[1], b0[3]);
                    imma(mid[mi][g * 2 + 0], a0[mi], b1[0], b1[2]);
                    imma(mid[mi][g * 2 + 1], a0[mi], b1[1], b1[3]);
                    imma(mid[mi][g * 2 + 0], a1[mi], b0[0], b0[2]);
                    imma(mid[mi][g * 2 + 1], a1[mi], b0[1], b0[3]);
                }
            }
        }
    }

    // ---- epilogue ----
    const int qr = lane >> 2;
    const int qc = (lane & 3) * 2;

    if (mode == 0) {
        const int sel = bx / 6;
        const int n0in = (bx % 6) * BN;
        __half* outp = (sel == 0) ? g_Q : (sel == 1) ? g_K : g_V;
        const float* bias = (sel == 0) ? bias_a : (sel == 1) ? bias_b : bias_c;
        #pragma unroll
        for (int mi = 0; mi < 2; mi++) {
            #pragma unroll
            for (int half = 0; half < 2; half++) {
                const int m = m0 + wm0 + mi * 16 + qr + half * 8;
                const float sa128 = Asc[m] * 128.f;
                float lmax = 0.f;
                #pragma unroll
                for (int n8 = 0; n8 < 4; n8++) {
                    const int nl = wn0 + n8 * 8 + qc;
                    const float sb0 = g_wsc[nrow0 + nl] * sa128;
                    const float sb1 = g_wsc[nrow0 + nl + 1] * sa128;
                    const int n = n0in + nl;
                    const size_t o = (size_t)m * Dq + n;
                    const int t0 = hi[mi][n8][half * 2 + 0] * 128 + mid[mi][n8][half * 2 + 0];
                    const int t1 = hi[mi][n8][half * 2 + 1] * 128 + mid[mi][n8][half * 2 + 1];
                    float2 v;
                    v.x = (float)t0 * sb0 + bias[n];
                    v.y = (float)t1 * sb1 + bias[n + 1];
                    *(__half2*)(outp + o) = __float22half2_rn(v);
                    lmax = fmaxf(lmax, fmaxf(fabsf(v.x), fabsf(v.y)));
                }
                if (sel == 2) {
                    lmax = fmaxf(lmax, __shfl_xor_sync(0xFFFFFFFFu, lmax, 1));
                    lmax = fmaxf(lmax, __shfl_xor_sync(0xFFFFFFFFu, lmax, 2));
                    if ((lane & 3) == 0)
                        atomicMax(&g_vmax[m], __float_as_uint(lmax));
                }
            }
        }
    } else {
        const int n0in = bx * BN;
        const float* bias = bias_a;
        #pragma unroll
        for (int mi = 0; mi < 2; mi++) {
            #pragma unroll
            for (int half = 0; half < 2; half++) {
                const int m = m0 + wm0 + mi * 16 + qr + half * 8;
                const float sa128 = Asc[m] * 128.f;
                #pragma unroll
                for (int n8 = 0; n8 < 4; n8++) {
                    const int nl = wn0 + n8 * 8 + qc;
                    const float sb0 = g_wsc[nrow0 + nl] * sa128;
                    const float sb1 = g_wsc[nrow0 + nl + 1] * sa128;
                    const int n = n0in + nl;
                    const size_t o = (size_t)m * Dq + n;
                    const int t0 = hi[mi][n8][half * 2 + 0] * 128 + mid[mi][n8][half * 2 + 0];
                    const int t1 = hi[mi][n8][half * 2 + 1] * 128 + mid[mi][n8][half * 2 + 1];
                    float2 v;
                    v.x = (float)t0 * sb0 + bias[n] + resid[o];
                    v.y = (float)t1 * sb1 + bias[n + 1] + resid[o + 1];
                    *(float2*)(g_Y + o) = v;
                }
            }
        }
    }
}

// ---------------------------------------------------------------------------
// Banded attention: 2 threads per position, fp16 Q/K/V (global), fp16 smem
// staging, writes int8 digits directly using precomputed row scale (g_ainv).
// ---------------------------------------------------------------------------
#define AT_TS 128
#define AT_HALO 132
#define AT_ROWH 70            // halves per row stride (140 B -> conflict-free half2)
#define ATT_SMEM (AT_HALO * AT_ROWH * 2)   // 18480 B

__global__ void __launch_bounds__(256) attn_kernel(
    const float* __restrict__ bk, const float* __restrict__ bv,
    int8_t* __restrict__ aq0, int8_t* __restrict__ aq1)
{
    extern __shared__ __half smh[];

    const int by = blockIdx.y;
    const int b  = by / Hq;
    const int h  = by % Hq;
    const int s0 = blockIdx.x * AT_TS;

    const size_t basep = ((size_t)b * Sq) * Dq + h * DHq;
    const int tid = threadIdx.x;
    const int si  = tid >> 1;          // position within tile
    const int hh  = tid & 1;           // dim half

    // ---- stage K (fp16 copy) ----
    {
        const __half* Kg = g_K + basep;
        const float* bsrc = bk + h * DHq;
        for (int idx = tid; idx < AT_HALO * 32; idx += 256) {
            const int r = idx >> 5;
            const int c2 = (idx & 31) * 2;
            const int gs = s0 - 2 + r;
            __half2 v = (gs >= 0 && gs < Sq)
                        ? *(const __half2*)(Kg + (size_t)gs * Dq + c2)
                        : __float22half2_rn(*(const float2*)(bsrc + c2));
            *(__half2*)&smh[r * AT_ROWH + c2] = v;
        }
    }
    __syncthreads();

    const __half2* qrow = (const __half2*)(g_Q + ((size_t)b * Sq + s0 + si) * Dq + h * DHq + hh * 32);
    float2 qv[16];
    #pragma unroll
    for (int d2 = 0; d2 < 16; d2++) qv[d2] = __half22float2(qrow[d2]);

    float sc[5];
    #pragma unroll
    for (int i = 0; i < 5; i++) {
        const __half2* krow = (const __half2*)&smh[(si + i) * AT_ROWH + hh * 32];
        float s = 0.f;
        #pragma unroll
        for (int d2 = 0; d2 < 16; d2++) {
            const float2 kf = __half22float2(krow[d2]);
            s += qv[d2].x * kf.x + qv[d2].y * kf.y;
        }
        sc[i] = s;
    }
    #pragma unroll
    for (int i = 0; i < 5; i++)
        sc[i] += __shfl_xor_sync(0xFFFFFFFFu, sc[i], 1);

    float mx = sc[0];
    #pragma unroll
    for (int i = 1; i < 5; i++) mx = fmaxf(mx, sc[i]);
    float p[5], sum = 0.f;
    #pragma unroll
    for (int i = 0; i < 5; i++) {
        p[i] = __expf((sc[i] - mx) * 0.125f);
        sum += p[i];
    }
    const float inv = 1.f / sum;
    #pragma unroll
    for (int i = 0; i < 5; i++) p[i] *= inv;

    // ---- stage V (reuse smem) ----
    __syncthreads();
    {
        const __half* Vg = g_V + basep;
        const float* bsrc = bv + h * DHq;
        for (int idx = tid; idx < AT_HALO * 32; idx += 256) {
            const int r = idx >> 5;
            const int c2 = (idx & 31) * 2;
            const int gs = s0 - 2 + r;
            __half2 v = (gs >= 0 && gs < Sq)
                        ? *(const __half2*)(Vg + (size_t)gs * Dq + c2)
                        : __float22half2_rn(*(const float2*)(bsrc + c2));
            *(__half2*)&smh[r * AT_ROWH + c2] = v;
        }
    }
    __syncthreads();

    float2 o2[16];
    #pragma unroll
    for (int d2 = 0; d2 < 16; d2++) { o2[d2].x = 0.f; o2[d2].y = 0.f; }
    #pragma unroll
    for (int i = 0; i < 5; i++) {
        const __half2* vrow = (const __half2*)&smh[(si + i) * AT_ROWH + hh * 32];
        const float pi = p[i];
        #pragma unroll
        for (int d2 = 0; d2 < 16; d2++) {
            const float2 vf = __half22float2(vrow[d2]);
            o2[d2].x += pi * vf.x;
            o2[d2].y += pi * vf.y;
        }
    }

    // ---- quantize in-register with precomputed row scale, write digits ----
    const int row = b * Sq + s0 + si;
    const float qinv = g_ainv[row];
    uint32_t p0[8], p1[8];
    #pragma unroll
    for (int d2 = 0; d2 < 8; d2++) {
        uint32_t w0 = 0, w1 = 0;
        #pragma unroll
        for (int j = 0; j < 2; j++) {
            const float2 o = o2[d2 * 2 + j];
            const int nx = __float2int_rn(o.x * qinv);
            const int ax0 = (nx + 64) >> 7;
            const int ax1 = nx - (ax0 << 7);
            const int ny = __float2int_rn(o.y * qinv);
            const int ay0 = (ny + 64) >> 7;
            const int ay1 = ny - (ay0 << 7);
            w0 |= ((uint32_t)(ax0 & 255) << (j * 16)) | ((uint32_t)(ay0 & 255) << (j * 16 + 8));
            w1 |= ((uint32_t)(ax1 & 255) << (j * 16)) | ((uint32_t)(ay1 & 255) << (j * 16 + 8));
        }
        p0[d2] = w0;
        p1[d2] = w1;
    }
    const size_t obase = (size_t)row * Dq + h * DHq + hh * 32;
    *(uint4*)(aq0 + obase)      = make_uint4(p0[0], p0[1], p0[2], p0[3]);
    *(uint4*)(aq0 + obase + 16) = make_uint4(p0[4], p0[5], p0[6], p0[7]);
    *(uint4*)(aq1 + obase)      = make_uint4(p1[0], p1[1], p1[2], p1[3]);
    *(uint4*)(aq1 + obase + 16) = make_uint4(p1[4], p1[5], p1[6], p1[7]);
}

// ---------------------------------------------------------------------------
// LayerNorm over last dim (768), float4 loads, 192 threads
// ---------------------------------------------------------------------------
__global__ void __launch_bounds__(192) ln_kernel(
    const float* __restrict__ gamma, const float* __restrict__ beta,
    float* __restrict__ outp)
{
    const int row = blockIdx.x;
    const float* y = g_Y + (size_t)row * Dq;
    const int tid = threadIdx.x;

    float4 v = *(const float4*)(y + tid * 4);
    float s  = v.x + v.y + v.z + v.w;
    float ss = v.x * v.x + v.y * v.y + v.z * v.z + v.w * v.w;
    #pragma unroll
    for (int o = 16; o > 0; o >>= 1) {
        s  += __shfl_xor_sync(0xFFFFFFFFu, s,  o);
        ss += __shfl_xor_sync(0xFFFFFFFFu, ss, o);
    }
    __shared__ float rs[6], rss[6];
    const int w = tid >> 5;
    if ((tid & 31) == 0) { rs[w] = s; rss[w] = ss; }
    __syncthreads();
    s  = rs[0] + rs[1] + rs[2] + rs[3] + rs[4] + rs[5];
    ss = rss[0] + rss[1] + rss[2] + rss[3] + rss[4] + rss[5];

    const float mu   = s * (1.f / 768.f);
    const float var  = ss * (1.f / 768.f) - mu * mu;
    const float rstd = rsqrtf(var + 1e-5f);

    const float4 g = *(const float4*)(gamma + tid * 4);
    const float4 be = *(const float4*)(beta + tid * 4);
    float4 o;
    o.x = (v.x - mu) * rstd * g.x + be.x;
    o.y = (v.y - mu) * rstd * g.y + be.y;
    o.z = (v.z - mu) * rstd * g.z + be.z;
    o.w = (v.w - mu) * rstd * g.w + be.w;
    *(float4*)(outp + (size_t)row * Dq + tid * 4) = o;
}

// ---------------------------------------------------------------------------
// Launch
// ---------------------------------------------------------------------------
extern "C" void kernel_launch(void* const* d_in, const int* in_sizes, int n_in,
                              void* d_out, int out_size)
{
    const float* x     = (const float*)d_in[0];
    const float* Wq    = (const float*)d_in[1];
    const float* bq    = (const float*)d_in[2];
    const float* Wk    = (const float*)d_in[3];
    const float* bk    = (const float*)d_in[4];
    const float* Wv    = (const float*)d_in[5];
    const float* bv    = (const float*)d_in[6];
    const float* Wo    = (const float*)d_in[7];
    const float* bo    = (const float*)d_in[8];
    const float* gamma = (const float*)d_in[9];
    const float* beta  = (const float*)d_in[10];
    float* out = (float*)d_out;

    static int configured = 0;
    if (!configured) {
        cudaFuncSetAttribute(ig_gemm_kernel,
                             cudaFuncAttributeMaxDynamicSharedMemorySize, GEMM_SMEM);
        cudaFuncSetAttribute(attn_kernel,
                             cudaFuncAttributeMaxDynamicSharedMemorySize, ATT_SMEM);
        configured = 1;
    }

    int8_t *xq0, *xq1, *aq0, *aq1;
    float *xsc, *asc;
    cudaGetSymbolAddress((void**)&xq0, g_xq0);
    cudaGetSymbolAddress((void**)&xq1, g_xq1);
    cudaGetSymbolAddress((void**)&xsc, g_xsc);
    cudaGetSymbolAddress((void**)&aq0, g_aq0);
    cudaGetSymbolAddress((void**)&aq1, g_aq1);
    cudaGetSymbolAddress((void**)&asc, g_asc);

    // 0) init + quantize inputs + weights
    init_kernel<<<Mq / 256, 256>>>(bv);
    quant_rows_kernel<<<Mq, 192>>>(x, xq0, xq1, xsc);
    wmax_kernel<<<dim3(3, 8, 4), 256>>>(Wq, Wk, Wv, Wo);
    wquant_kernel<<<dim3(24, 24, 4), 256>>>(Wq, Wk, Wv, Wo);

    // 1) QKV projections (fp16 out, + V row absmax atomics)
    ig_gemm_kernel<<<dim3(18, Mq / BM), 256, GEMM_SMEM>>>(
        xq0, xq1, xsc, bq, bk, bv, nullptr, 0, 0);

    // 2) per-row att scale bound, then fused attention+quant
    vscale_kernel<<<Mq / 256, 256>>>();
    attn_kernel<<<dim3(Sq / AT_TS, Bq * Hq), 256, ATT_SMEM>>>(bk, bv, aq0, aq1);

    // 3) O projection + bias + residual -> g_Y
    ig_gemm_kernel<<<dim3(6, Mq / BM), 256, GEMM_SMEM>>>(
        aq0, aq1, asc, bo, nullptr, nullptr, x, 3 * Dq, 1);

    // 4) LayerNorm -> d_out
    ln_kernel<<<Mq, 192>>>(gamma, beta, out);
}

// round 10
// speedup vs baseline: 1.9496x; 1.0280x over previous
#include <cuda_runtime.h>
#include <cuda_fp16.h>
#include <cstdint>

// Problem constants
#define Bq 8
#define Sq 4096
#define Dq 768
#define Hq 12
#define DHq 64
#define Mq (Bq * Sq)          // 32768 rows

// int8 GEMM tiling (mma.sync m16n8k32 s8 -> s32)
#define BM 64
#define BN 128
#define BK 64                 // int8 K elements per chunk
#define NCHUNK 12             // 768/64
// Swizzled 64B rows, no padding. seg' = seg ^ ((row>>1)&3), 16B segments.
#define A0_OFF 0
#define A1_OFF 4096
#define B0_OFF 8192
#define B1_OFF 16384
#define STAGE_B 24576
#define NSTAGE 3
#define GEMM_SMEM (NSTAGE * STAGE_B)   // 73728 -> 2 CTAs/SM

#define QMAX 16256.0f         // 127*128

// ---------------------------------------------------------------------------
// Scratch (device globals)
// ---------------------------------------------------------------------------
__device__ __half g_Q[(size_t)Mq * Dq];
__device__ __half g_K[(size_t)Mq * Dq];
__device__ __half g_V[(size_t)Mq * Dq];
__device__ float  g_Y[(size_t)Mq * Dq];
__device__ int8_t g_xq0[(size_t)Mq * Dq];
__device__ int8_t g_xq1[(size_t)Mq * Dq];
__device__ float  g_xsc[Mq];
__device__ int8_t g_aq0[(size_t)Mq * Dq];
__device__ int8_t g_aq1[(size_t)Mq * Dq];
__device__ float  g_asc[Mq];      // att row scale (amax/QMAX), written by attn
__device__ unsigned int g_vmax[Mq];
__device__ float  g_bvmax;
__device__ int8_t g_wq0[(size_t)4 * Dq * Dq];   // transposed [n][k]; rows: Wq|Wk|Wv|Wo
__device__ int8_t g_wq1[(size_t)4 * Dq * Dq];
__device__ float  g_wsc[4 * Dq];
__device__ unsigned int g_wmax[4 * Dq];

// ---------------------------------------------------------------------------
// PTX helpers
// ---------------------------------------------------------------------------
__device__ __forceinline__ uint32_t smem_u32(const void* p) {
    uint32_t a;
    asm("{ .reg .u64 t; cvta.to.shared.u64 t, %1; cvt.u32.u64 %0, t; }" : "=r"(a) : "l"(p));
    return a;
}
__device__ __forceinline__ void cp16(uint32_t dst, const void* src) {
    asm volatile("cp.async.cg.shared.global [%0], [%1], 16;" :: "r"(dst), "l"(src) : "memory");
}
__device__ __forceinline__ void cp_commit() { asm volatile("cp.async.commit_group;" ::: "memory"); }
__device__ __forceinline__ void cp_wait1()  { asm volatile("cp.async.wait_group 1;" ::: "memory"); }
__device__ __forceinline__ void cp_wait0()  { asm volatile("cp.async.wait_group 0;" ::: "memory"); }

__device__ __forceinline__ void ldsm_x4(uint32_t (&r)[4], uint32_t addr) {
    asm volatile("ldmatrix.sync.aligned.m8n8.x4.shared.b16 {%0,%1,%2,%3}, [%4];"
                 : "=r"(r[0]), "=r"(r[1]), "=r"(r[2]), "=r"(r[3]) : "r"(addr));
}
// D += A(s8 m16k32) * B(s8 n8k32), s32 accumulate
__device__ __forceinline__ void imma(int (&d)[4], const uint32_t (&a)[4],
                                     uint32_t b0, uint32_t b1) {
    asm volatile("mma.sync.aligned.m16n8k32.row.col.s32.s8.s8.s32 "
                 "{%0,%1,%2,%3}, {%4,%5,%6,%7}, {%8,%9}, {%0,%1,%2,%3};"
                 : "+r"(d[0]), "+r"(d[1]), "+r"(d[2]), "+r"(d[3])
                 : "r"(a[0]), "r"(a[1]), "r"(a[2]), "r"(a[3]), "r"(b0), "r"(b1));
}

// ---------------------------------------------------------------------------
// Row quantizer (float4, 192 threads): per-row absmax -> 2-digit int8
// ---------------------------------------------------------------------------
__global__ void __launch_bounds__(192) quant_rows_kernel(
    const float* __restrict__ src, int8_t* __restrict__ q0,
    int8_t* __restrict__ q1, float* __restrict__ scl)
{
    const int row = blockIdx.x;
    const int tid = threadIdx.x;
    const float4 v = *(const float4*)(src + (size_t)row * Dq + tid * 4);

    float mx = fmaxf(fmaxf(fabsf(v.x), fabsf(v.y)), fmaxf(fabsf(v.z), fabsf(v.w)));
    #pragma unroll
    for (int o = 16; o > 0; o >>= 1)
        mx = fmaxf(mx, __shfl_xor_sync(0xFFFFFFFFu, mx, o));
    __shared__ float rm[6];
    if ((tid & 31) == 0) rm[tid >> 5] = mx;
    __syncthreads();
    mx = fmaxf(fmaxf(fmaxf(rm[0], rm[1]), fmaxf(rm[2], rm[3])), fmaxf(rm[4], rm[5]));

    const float inv = (mx > 0.f) ? (QMAX / mx) : 0.f;
    if (tid == 0) scl[row] = (mx > 0.f) ? (mx / QMAX) : 0.f;

    const float f[4] = {v.x, v.y, v.z, v.w};
    uint32_t w0 = 0, w1 = 0;
    #pragma unroll
    for (int j = 0; j < 4; j++) {
        const int n = __float2int_rn(f[j] * inv);
        const int a0 = (n + 64) >> 7;
        const int a1 = n - (a0 << 7);
        w0 |= (uint32_t)(a0 & 255) << (j * 8);
        w1 |= (uint32_t)(a1 & 255) << (j * 8);
    }
    *(uint32_t*)(q0 + (size_t)row * Dq + tid * 4) = w0;
    *(uint32_t*)(q1 + (size_t)row * Dq + tid * 4) = w1;
}

// ---------------------------------------------------------------------------
// Merged init: zero vmax + wmax; last block reduces |bv|
// ---------------------------------------------------------------------------
__global__ void __launch_bounds__(256) init_kernel(const float* __restrict__ bv) {
    const int blk = blockIdx.x;
    const int tid = threadIdx.x;
    const int i = blk * 256 + tid;
    if (i < Mq) g_vmax[i] = 0u;
    if (i < 4 * Dq) g_wmax[i] = 0u;
    if (blk == gridDim.x - 1) {
        float mx = fmaxf(fmaxf(fabsf(bv[tid]), fabsf(bv[tid + 256])), fabsf(bv[tid + 512]));
        #pragma unroll
        for (int o = 16; o > 0; o >>= 1)
            mx = fmaxf(mx, __shfl_xor_sync(0xFFFFFFFFu, mx, o));
        __shared__ float rm[8];
        if ((tid & 31) == 0) rm[tid >> 5] = mx;
        __syncthreads();
        if (tid == 0) {
            mx = fmaxf(fmaxf(fmaxf(rm[0], rm[1]), fmaxf(rm[2], rm[3])),
                       fmaxf(fmaxf(rm[4], rm[5]), fmaxf(rm[6], rm[7])));
            g_bvmax = mx;
        }
    }
}

// ---------------------------------------------------------------------------
// Weight absmax per output column (atomicMax on positive float bits)
// ---------------------------------------------------------------------------
__global__ void __launch_bounds__(256) wmax_kernel(
    const float* __restrict__ Wq, const float* __restrict__ Wk,
    const float* __restrict__ Wv, const float* __restrict__ Wo)
{
    const int w = blockIdx.z;
    const float* W = (w == 0) ? Wq : (w == 1) ? Wk : (w == 2) ? Wv : Wo;
    const int n = blockIdx.x * 256 + threadIdx.x;
    const int k0 = blockIdx.y * 96;
    float mx = 0.f;
    for (int j = 0; j < 96; j++)
        mx = fmaxf(mx, fabsf(W[(size_t)(k0 + j) * Dq + n]));
    atomicMax(&g_wmax[w * Dq + n], __float_as_uint(mx));
}

// ---------------------------------------------------------------------------
// Weight quantize + transpose: out[n][k] digits
// ---------------------------------------------------------------------------
__global__ void __launch_bounds__(256) wquant_kernel(
    const float* __restrict__ Wq, const float* __restrict__ Wk,
    const float* __restrict__ Wv, const float* __restrict__ Wo)
{
    __shared__ float t[32][33];
    const int w = blockIdx.z;
    const float* W = (w == 0) ? Wq : (w == 1) ? Wk : (w == 2) ? Wv : Wo;
    const int n0 = blockIdx.x * 32, k0 = blockIdx.y * 32;
    const int tx = threadIdx.x & 31, ty = threadIdx.x >> 5;

    #pragma unroll
    for (int i = 0; i < 4; i++)
        t[ty + i * 8][tx] = W[(size_t)(k0 + ty + i * 8) * Dq + n0 + tx];
    __syncthreads();
    #pragma unroll
    for (int i = 0; i < 4; i++) {
        const int n = n0 + ty + i * 8;
        const float mx = __uint_as_float(g_wmax[w * Dq + n]);
        const float inv = (mx > 0.f) ? (QMAX / mx) : 0.f;
        if (k0 == 0 && tx == 0)
            g_wsc[w * Dq + n] = (mx > 0.f) ? (mx / QMAX) : 0.f;
        const float val = t[tx][ty + i * 8];        // W[k0+tx][n]
        const int q = __float2int_rn(val * inv);
        const int a0 = (q + 64) >> 7;
        const int a1 = q - (a0 << 7);
        const size_t o = (size_t)(w * Dq + n) * Dq + k0 + tx;
        g_wq0[o] = (int8_t)a0;
        g_wq1[o] = (int8_t)a1;
    }
}

// ---------------------------------------------------------------------------
// int8 tensor-core GEMM (R7-proven): C[64 x 128] = A @ W^T, 3 IMMA products.
// mode 0: outputs Q|K|V as fp16 (+bias) and V-row absmax atomics, grid (18, 512)
// mode 1: g_Y = C + bo + resid (fp32), grid (6, 512)
// ---------------------------------------------------------------------------
__global__ void __launch_bounds__(256, 2) ig_gemm_kernel(
    const int8_t* __restrict__ Aq0, const int8_t* __restrict__ Aq1,
    const float* __restrict__ Asc,
    const float* __restrict__ bias_a, const float* __restrict__ bias_b,
    const float* __restrict__ bias_c, const float* __restrict__ resid,
    int wbase, int mode)
{
    extern __shared__ __align__(128) char smem_raw[];
    const uint32_t base = smem_u32(smem_raw);

    const int tid  = threadIdx.x;
    const int wid  = tid >> 5;
    const int lane = tid & 31;
    const int m0 = blockIdx.y * BM;
    const int bx = blockIdx.x;
    const int nrow0 = wbase + bx * BN;

    const int wm0 = (wid & 1) * 32;          // 2 warps in M
    const int wn0 = (wid >> 1) * 32;         // 4 warps in N

    const int rA   = tid >> 2;
    const int sgA  = tid & 3;
    const uint32_t soA = (uint32_t)(rA * 64 + ((sgA ^ ((rA >> 1) & 3)) << 4));

    auto load_stage = [&](int c, int s) {
        const int k0 = c * BK;
        const uint32_t sb = base + (uint32_t)s * STAGE_B;
        cp16(sb + A0_OFF + soA, Aq0 + (size_t)(m0 + rA) * Dq + k0 + sgA * 16);
        cp16(sb + A1_OFF + soA, Aq1 + (size_t)(m0 + rA) * Dq + k0 + sgA * 16);
        #pragma unroll
        for (int half = 0; half < 2; half++) {
            const int u = tid + half * 256;
            const int rB = u >> 2, sgB = u & 3;
            const uint32_t soB = (uint32_t)(rB * 64 + ((sgB ^ ((rB >> 1) & 3)) << 4));
            cp16(sb + B0_OFF + soB, g_wq0 + (size_t)(nrow0 + rB) * Dq + k0 + sgB * 16);
            cp16(sb + B1_OFF + soB, g_wq1 + (size_t)(nrow0 + rB) * Dq + k0 + sgB * 16);
        }
        cp_commit();
    };

    int hi[2][4][4], mid[2][4][4];
    #pragma unroll
    for (int mi = 0; mi < 2; mi++)
        #pragma unroll
        for (int n8 = 0; n8 < 4; n8++)
            #pragma unroll
            for (int j = 0; j < 4; j++) { hi[mi][n8][j] = 0; mid[mi][n8][j] = 0; }

    const int lrow = (lane & 7) + ((lane >> 3) & 1) * 8;
    const int lkseg = (lane >> 4);

    load_stage(0, 0);
    load_stage(1, 1);

    for (int c = 0; c < NCHUNK; c++) {
        if (c + 1 < NCHUNK) cp_wait1();
        else                cp_wait0();
        __syncthreads();
        if (c + 2 < NCHUNK) load_stage(c + 2, (c + 2) % NSTAGE);

        const uint32_t sb = base + (uint32_t)(c % NSTAGE) * STAGE_B;
        const uint32_t sA0 = sb + A0_OFF, sA1 = sb + A1_OFF;
        const uint32_t sB0 = sb + B0_OFF, sB1 = sb + B1_OFF;

        #pragma unroll
        for (int ks = 0; ks < 2; ks++) {
            const int segk = ks * 2 + lkseg;
            uint32_t a0[2][4], a1[2][4];
            #pragma unroll
            for (int mi = 0; mi < 2; mi++) {
                const int row = wm0 + mi * 16 + lrow;
                const uint32_t ro = (uint32_t)(row * 64 + ((segk ^ ((row >> 1) & 3)) << 4));
                ldsm_x4(a0[mi], sA0 + ro);
                ldsm_x4(a1[mi], sA1 + ro);
            }
            #pragma unroll
            for (int g = 0; g < 2; g++) {
                uint32_t b0[4], b1[4];
                const int row = wn0 + g * 16 + lrow;
                const uint32_t ro = (uint32_t)(row * 64 + ((segk ^ ((row >> 1) & 3)) << 4));
                ldsm_x4(b0, sB0 + ro);
                ldsm_x4(b1, sB1 + ro);
                #pragma unroll
                for (int mi = 0; mi < 2; mi++) {
                    imma(hi[mi][g * 2 + 0], a0[mi], b0[0], b0[2]);
                    imma(hi[mi][g * 2 + 1], a0[mi], b0[1], b0[3]);
                    imma(mid[mi][g * 2 + 0], a0[mi], b1[0], b1[2]);
                    imma(mid[mi][g * 2 + 1], a0[mi], b1[1], b1[3]);
                    imma(mid[mi][g * 2 + 0], a1[mi], b0[0], b0[2]);
                    imma(mid[mi][g * 2 + 1], a1[mi], b0[1], b0[3]);
                }
            }
        }
    }

    // ---- epilogue ----
    const int qr = lane >> 2;
    const int qc = (lane & 3) * 2;

    if (mode == 0) {
        const int sel = bx / 6;
        const int n0in = (bx % 6) * BN;
        __half* outp = (sel == 0) ? g_Q : (sel == 1) ? g_K : g_V;
        const float* bias = (sel == 0) ? bias_a : (sel == 1) ? bias_b : bias_c;
        #pragma unroll
        for (int mi = 0; mi < 2; mi++) {
            #pragma unroll
            for (int half = 0; half < 2; half++) {
                const int m = m0 + wm0 + mi * 16 + qr + half * 8;
                const float sa128 = Asc[m] * 128.f;
                float lmax = 0.f;
                #pragma unroll
                for (int n8 = 0; n8 < 4; n8++) {
                    const int nl = wn0 + n8 * 8 + qc;
                    const float sb0 = g_wsc[nrow0 + nl] * sa128;
                    const float sb1 = g_wsc[nrow0 + nl + 1] * sa128;
                    const int n = n0in + nl;
                    const size_t o = (size_t)m * Dq + n;
                    const int t0 = hi[mi][n8][half * 2 + 0] * 128 + mid[mi][n8][half * 2 + 0];
                    const int t1 = hi[mi][n8][half * 2 + 1] * 128 + mid[mi][n8][half * 2 + 1];
                    float2 v;
                    v.x = (float)t0 * sb0 + bias[n];
                    v.y = (float)t1 * sb1 + bias[n + 1];
                    *(__half2*)(outp + o) = __float22half2_rn(v);
                    lmax = fmaxf(lmax, fmaxf(fabsf(v.x), fabsf(v.y)));
                }
                if (sel == 2) {
                    lmax = fmaxf(lmax, __shfl_xor_sync(0xFFFFFFFFu, lmax, 1));
                    lmax = fmaxf(lmax, __shfl_xor_sync(0xFFFFFFFFu, lmax, 2));
                    if ((lane & 3) == 0)
                        atomicMax(&g_vmax[m], __float_as_uint(lmax));
                }
            }
        }
    } else {
        const int n0in = bx * BN;
        const float* bias = bias_a;
        #pragma unroll
        for (int mi = 0; mi < 2; mi++) {
            #pragma unroll
            for (int half = 0; half < 2; half++) {
                const int m = m0 + wm0 + mi * 16 + qr + half * 8;
                const float sa128 = Asc[m] * 128.f;
                #pragma unroll
                for (int n8 = 0; n8 < 4; n8++) {
                    const int nl = wn0 + n8 * 8 + qc;
                    const float sb0 = g_wsc[nrow0 + nl] * sa128;
                    const float sb1 = g_wsc[nrow0 + nl + 1] * sa128;
                    const int n = n0in + nl;
                    const size_t o = (size_t)m * Dq + n;
                    const int t0 = hi[mi][n8][half * 2 + 0] * 128 + mid[mi][n8][half * 2 + 0];
                    const int t1 = hi[mi][n8][half * 2 + 1] * 128 + mid[mi][n8][half * 2 + 1];
                    float2 v;
                    v.x = (float)t0 * sb0 + bias[n] + resid[o];
                    v.y = (float)t1 * sb1 + bias[n + 1] + resid[o + 1];
                    *(float2*)(g_Y + o) = v;
                }
            }
        }
    }
}

// ---------------------------------------------------------------------------
// Banded attention: single-phase K+V staging (1 barrier), inline vscale
// from the g_vmax window, int8 digit output. 2 threads per position.
// ---------------------------------------------------------------------------
#define AT_TS 128
#define AT_HALO 132
#define AT_ROWH 70            // halves per row stride (140 B -> conflict-free half2)
#define ATT_SMEM (2 * AT_HALO * AT_ROWH * 2)   // Ks + Vs = 36960 B

__global__ void __launch_bounds__(256) attn_kernel(
    const float* __restrict__ bk, const float* __restrict__ bv,
    int8_t* __restrict__ aq0, int8_t* __restrict__ aq1)
{
    extern __shared__ __half smh[];
    __half* Ks = smh;
    __half* Vs = smh + AT_HALO * AT_ROWH;

    const int by = blockIdx.y;
    const int b  = by / Hq;
    const int h  = by % Hq;
    const int s0 = blockIdx.x * AT_TS;

    const size_t basep = ((size_t)b * Sq) * Dq + h * DHq;
    const int tid = threadIdx.x;
    const int si  = tid >> 1;          // position within tile
    const int hh  = tid & 1;           // dim half

    // ---- stage K and V together (one barrier total) ----
    {
        const __half* Kg = g_K + basep;
        const __half* Vg = g_V + basep;
        const float* bks = bk + h * DHq;
        const float* bvs = bv + h * DHq;
        for (int idx = tid; idx < AT_HALO * 32; idx += 256) {
            const int r = idx >> 5;
            const int c2 = (idx & 31) * 2;
            const int gs = s0 - 2 + r;
            __half2 kv, vv;
            if (gs >= 0 && gs < Sq) {
                kv = *(const __half2*)(Kg + (size_t)gs * Dq + c2);
                vv = *(const __half2*)(Vg + (size_t)gs * Dq + c2);
            } else {
                kv = __float22half2_rn(*(const float2*)(bks + c2));
                vv = __float22half2_rn(*(const float2*)(bvs + c2));
            }
            *(__half2*)&Ks[r * AT_ROWH + c2] = kv;
            *(__half2*)&Vs[r * AT_ROWH + c2] = vv;
        }
    }
    __syncthreads();

    const int row = b * Sq + s0 + si;
    const __half2* qrow = (const __half2*)(g_Q + (size_t)row * Dq + h * DHq + hh * 32);
    float2 qv[16];
    #pragma unroll
    for (int d2 = 0; d2 < 16; d2++) qv[d2] = __half22float2(qrow[d2]);

    float sc[5];
    #pragma unroll
    for (int i = 0; i < 5; i++) {
        const __half2* krow = (const __half2*)&Ks[(si + i) * AT_ROWH + hh * 32];
        float s = 0.f;
        #pragma unroll
        for (int d2 = 0; d2 < 16; d2++) {
            const float2 kf = __half22float2(krow[d2]);
            s += qv[d2].x * kf.x + qv[d2].y * kf.y;
        }
        sc[i] = s;
    }
    #pragma unroll
    for (int i = 0; i < 5; i++)
        sc[i] += __shfl_xor_sync(0xFFFFFFFFu, sc[i], 1);

    float mx = sc[0];
    #pragma unroll
    for (int i = 1; i < 5; i++) mx = fmaxf(mx, sc[i]);
    float p[5], sum = 0.f;
    #pragma unroll
    for (int i = 0; i < 5; i++) {
        p[i] = __expf((sc[i] - mx) * 0.125f);
        sum += p[i];
    }
    const float inv = 1.f / sum;
    #pragma unroll
    for (int i = 0; i < 5; i++) p[i] *= inv;

    float2 o2[16];
    #pragma unroll
    for (int d2 = 0; d2 < 16; d2++) { o2[d2].x = 0.f; o2[d2].y = 0.f; }
    #pragma unroll
    for (int i = 0; i < 5; i++) {
        const __half2* vrow = (const __half2*)&Vs[(si + i) * AT_ROWH + hh * 32];
        const float pi = p[i];
        #pragma unroll
        for (int d2 = 0; d2 < 16; d2++) {
            const float2 vf = __half22float2(vrow[d2]);
            o2[d2].x += pi * vf.x;
            o2[d2].y += pi * vf.y;
        }
    }

    // ---- inline vscale: bound amax by the V-row window + |bv| ----
    const int sloc = s0 + si;
    float amax = g_bvmax;
    #pragma unroll
    for (int i = -2; i <= 2; i++) {
        const int ss = sloc + i;
        if (ss >= 0 && ss < Sq)
            amax = fmaxf(amax, __uint_as_float(g_vmax[(b << 12) + ss]));
    }
    if (amax <= 0.f) amax = 1e-20f;
    const float qinv = QMAX / amax;
    if (hh == 0) g_asc[row] = amax / QMAX;

    // ---- quantize in-register, write digits ----
    uint32_t p0[8], p1[8];
    #pragma unroll
    for (int d2 = 0; d2 < 8; d2++) {
        uint32_t w0 = 0, w1 = 0;
        #pragma unroll
        for (int j = 0; j < 2; j++) {
            const float2 o = o2[d2 * 2 + j];
            const int nx = __float2int_rn(o.x * qinv);
            const int ax0 = (nx + 64) >> 7;
            const int ax1 = nx - (ax0 << 7);
            const int ny = __float2int_rn(o.y * qinv);
            const int ay0 = (ny + 64) >> 7;
            const int ay1 = ny - (ay0 << 7);
            w0 |= ((uint32_t)(ax0 & 255) << (j * 16)) | ((uint32_t)(ay0 & 255) << (j * 16 + 8));
            w1 |= ((uint32_t)(ax1 & 255) << (j * 16)) | ((uint32_t)(ay1 & 255) << (j * 16 + 8));
        }
        p0[d2] = w0;
        p1[d2] = w1;
    }
    const size_t obase = (size_t)row * Dq + h * DHq + hh * 32;
    *(uint4*)(aq0 + obase)      = make_uint4(p0[0], p0[1], p0[2], p0[3]);
    *(uint4*)(aq0 + obase + 16) = make_uint4(p0[4], p0[5], p0[6], p0[7]);
    *(uint4*)(aq1 + obase)      = make_uint4(p1[0], p1[1], p1[2], p1[3]);
    *(uint4*)(aq1 + obase + 16) = make_uint4(p1[4], p1[5], p1[6], p1[7]);
}

// ---------------------------------------------------------------------------
// LayerNorm over last dim (768), float4 loads, 192 threads
// ---------------------------------------------------------------------------
__global__ void __launch_bounds__(192) ln_kernel(
    const float* __restrict__ gamma, const float* __restrict__ beta,
    float* __restrict__ outp)
{
    const int row = blockIdx.x;
    const float* y = g_Y + (size_t)row * Dq;
    const int tid = threadIdx.x;

    float4 v = *(const float4*)(y + tid * 4);
    float s  = v.x + v.y + v.z + v.w;
    float ss = v.x * v.x + v.y * v.y + v.z * v.z + v.w * v.w;
    #pragma unroll
    for (int o = 16; o > 0; o >>= 1) {
        s  += __shfl_xor_sync(0xFFFFFFFFu, s,  o);
        ss += __shfl_xor_sync(0xFFFFFFFFu, ss, o);
    }
    __shared__ float rs[6], rss[6];
    const int w = tid >> 5;
    if ((tid & 31) == 0) { rs[w] = s; rss[w] = ss; }
    __syncthreads();
    s  = rs[0] + rs[1] + rs[2] + rs[3] + rs[4] + rs[5];
    ss = rss[0] + rss[1] + rss[2] + rss[3] + rss[4] + rss[5];

    const float mu   = s * (1.f / 768.f);
    const float var  = ss * (1.f / 768.f) - mu * mu;
    const float rstd = rsqrtf(var + 1e-5f);

    const float4 g = *(const float4*)(gamma + tid * 4);
    const float4 be = *(const float4*)(beta + tid * 4);
    float4 o;
    o.x = (v.x - mu) * rstd * g.x + be.x;
    o.y = (v.y - mu) * rstd * g.y + be.y;
    o.z = (v.z - mu) * rstd * g.z + be.z;
    o.w = (v.w - mu) * rstd * g.w + be.w;
    *(float4*)(outp + (size_t)row * Dq + tid * 4) = o;
}

// ---------------------------------------------------------------------------
// Launch
// ---------------------------------------------------------------------------
extern "C" void kernel_launch(void* const* d_in, const int* in_sizes, int n_in,
                              void* d_out, int out_size)
{
    const float* x     = (const float*)d_in[0];
    const float* Wq    = (const float*)d_in[1];
    const float* bq    = (const float*)d_in[2];
    const float* Wk    = (const float*)d_in[3];
    const float* bk    = (const float*)d_in[4];
    const float* Wv    = (const float*)d_in[5];
    const float* bv    = (const float*)d_in[6];
    const float* Wo    = (const float*)d_in[7];
    const float* bo    = (const float*)d_in[8];
    const float* gamma = (const float*)d_in[9];
    const float* beta  = (const float*)d_in[10];
    float* out = (float*)d_out;

    static int configured = 0;
    if (!configured) {
        cudaFuncSetAttribute(ig_gemm_kernel,
                             cudaFuncAttributeMaxDynamicSharedMemorySize, GEMM_SMEM);
        cudaFuncSetAttribute(attn_kernel,
                             cudaFuncAttributeMaxDynamicSharedMemorySize, ATT_SMEM);
        configured = 1;
    }

    int8_t *xq0, *xq1, *aq0, *aq1;
    float *xsc, *asc;
    cudaGetSymbolAddress((void**)&xq0, g_xq0);
    cudaGetSymbolAddress((void**)&xq1, g_xq1);
    cudaGetSymbolAddress((void**)&xsc, g_xsc);
    cudaGetSymbolAddress((void**)&aq0, g_aq0);
    cudaGetSymbolAddress((void**)&aq1, g_aq1);
    cudaGetSymbolAddress((void**)&asc, g_asc);

    // 0) init + quantize inputs + weights
    init_kernel<<<Mq / 256, 256>>>(bv);
    quant_rows_kernel<<<Mq, 192>>>(x, xq0, xq1, xsc);
    wmax_kernel<<<dim3(3, 8, 4), 256>>>(Wq, Wk, Wv, Wo);
    wquant_kernel<<<dim3(24, 24, 4), 256>>>(Wq, Wk, Wv, Wo);

    // 1) QKV projections (fp16 out, + V row absmax atomics)
    ig_gemm_kernel<<<dim3(18, Mq / BM), 256, GEMM_SMEM>>>(
        xq0, xq1, xsc, bq, bk, bv, nullptr, 0, 0);

    // 2) fused attention + inline vscale + quant
    attn_kernel<<<dim3(Sq / AT_TS, Bq * Hq), 256, ATT_SMEM>>>(bk, bv, aq0, aq1);

    // 3) O projection + bias + residual -> g_Y
    ig_gemm_kernel<<<dim3(6, Mq / BM), 256, GEMM_SMEM>>>(
        aq0, aq1, asc, bo, nullptr, nullptr, x, 3 * Dq, 1);

    // 4) LayerNorm -> d_out
    ln_kernel<<<Mq, 192>>>(gamma, beta, out);
}

// round 11
// speedup vs baseline: 1.9624x; 1.0066x over previous
#include <cuda_runtime.h>
#include <cuda_fp16.h>
#include <cstdint>

// Problem constants
#define Bq 8
#define Sq 4096
#define Dq 768
#define Hq 12
#define DHq 64
#define Mq (Bq * Sq)          // 32768 rows

// int8 GEMM tiling (mma.sync m16n8k32 s8 -> s32)
#define BM 64
#define BN 128
#define BK 64                 // int8 K elements per chunk
#define NCHUNK 12             // 768/64
// Swizzled 64B rows, no padding. seg' = seg ^ ((row>>1)&3), 16B segments.
#define A0_OFF 0
#define A1_OFF 4096
#define B0_OFF 8192
#define B1_OFF 16384
#define STAGE_B 24576
#define NSTAGE 3
#define GEMM_SMEM (NSTAGE * STAGE_B)   // 73728 -> 2 CTAs/SM

#define QMAX 16256.0f         // 127*128

// ---------------------------------------------------------------------------
// Scratch (device globals)
// ---------------------------------------------------------------------------
__device__ __half g_Q[(size_t)Mq * Dq];
__device__ __half g_K[(size_t)Mq * Dq];
__device__ __half g_V[(size_t)Mq * Dq];
__device__ float  g_Y[(size_t)Mq * Dq];
__device__ int8_t g_xq0[(size_t)Mq * Dq];
__device__ int8_t g_xq1[(size_t)Mq * Dq];
__device__ float  g_xsc[Mq];
__device__ int8_t g_aq0[(size_t)Mq * Dq];
__device__ int8_t g_aq1[(size_t)Mq * Dq];
__device__ float  g_asc[Mq];      // att row scale (amax/QMAX), written by attn
__device__ unsigned int g_vmax[Mq];
__device__ float  g_bvmax;
__device__ int8_t g_wq0[(size_t)4 * Dq * Dq];   // transposed [n][k]; rows: Wq|Wk|Wv|Wo
__device__ int8_t g_wq1[(size_t)4 * Dq * Dq];
__device__ float  g_wsc[4 * Dq];
__device__ unsigned int g_wmax[4 * Dq];

// ---------------------------------------------------------------------------
// PTX helpers
// ---------------------------------------------------------------------------
__device__ __forceinline__ uint32_t smem_u32(const void* p) {
    uint32_t a;
    asm("{ .reg .u64 t; cvta.to.shared.u64 t, %1; cvt.u32.u64 %0, t; }" : "=r"(a) : "l"(p));
    return a;
}
__device__ __forceinline__ void cp16(uint32_t dst, const void* src) {
    asm volatile("cp.async.cg.shared.global [%0], [%1], 16;" :: "r"(dst), "l"(src) : "memory");
}
__device__ __forceinline__ void cp_commit() { asm volatile("cp.async.commit_group;" ::: "memory"); }
__device__ __forceinline__ void cp_wait1()  { asm volatile("cp.async.wait_group 1;" ::: "memory"); }
__device__ __forceinline__ void cp_wait0()  { asm volatile("cp.async.wait_group 0;" ::: "memory"); }

__device__ __forceinline__ void ldsm_x4(uint32_t (&r)[4], uint32_t addr) {
    asm volatile("ldmatrix.sync.aligned.m8n8.x4.shared.b16 {%0,%1,%2,%3}, [%4];"
                 : "=r"(r[0]), "=r"(r[1]), "=r"(r[2]), "=r"(r[3]) : "r"(addr));
}
// D += A(s8 m16k32) * B(s8 n8k32), s32 accumulate
__device__ __forceinline__ void imma(int (&d)[4], const uint32_t (&a)[4],
                                     uint32_t b0, uint32_t b1) {
    asm volatile("mma.sync.aligned.m16n8k32.row.col.s32.s8.s8.s32 "
                 "{%0,%1,%2,%3}, {%4,%5,%6,%7}, {%8,%9}, {%0,%1,%2,%3};"
                 : "+r"(d[0]), "+r"(d[1]), "+r"(d[2]), "+r"(d[3])
                 : "r"(a[0]), "r"(a[1]), "r"(a[2]), "r"(a[3]), "r"(b0), "r"(b1));
}

// ---------------------------------------------------------------------------
// Row quantizer (float4, 192 threads): per-row absmax -> 2-digit int8
// ---------------------------------------------------------------------------
__global__ void __launch_bounds__(192) quant_rows_kernel(
    const float* __restrict__ src, int8_t* __restrict__ q0,
    int8_t* __restrict__ q1, float* __restrict__ scl)
{
    const int row = blockIdx.x;
    const int tid = threadIdx.x;
    const float4 v = *(const float4*)(src + (size_t)row * Dq + tid * 4);

    float mx = fmaxf(fmaxf(fabsf(v.x), fabsf(v.y)), fmaxf(fabsf(v.z), fabsf(v.w)));
    #pragma unroll
    for (int o = 16; o > 0; o >>= 1)
        mx = fmaxf(mx, __shfl_xor_sync(0xFFFFFFFFu, mx, o));
    __shared__ float rm[6];
    if ((tid & 31) == 0) rm[tid >> 5] = mx;
    __syncthreads();
    mx = fmaxf(fmaxf(fmaxf(rm[0], rm[1]), fmaxf(rm[2], rm[3])), fmaxf(rm[4], rm[5]));

    const float inv = (mx > 0.f) ? (QMAX / mx) : 0.f;
    if (tid == 0) scl[row] = (mx > 0.f) ? (mx / QMAX) : 0.f;

    const float f[4] = {v.x, v.y, v.z, v.w};
    uint32_t w0 = 0, w1 = 0;
    #pragma unroll
    for (int j = 0; j < 4; j++) {
        const int n = __float2int_rn(f[j] * inv);
        const int a0 = (n + 64) >> 7;
        const int a1 = n - (a0 << 7);
        w0 |= (uint32_t)(a0 & 255) << (j * 8);
        w1 |= (uint32_t)(a1 & 255) << (j * 8);
    }
    *(uint32_t*)(q0 + (size_t)row * Dq + tid * 4) = w0;
    *(uint32_t*)(q1 + (size_t)row * Dq + tid * 4) = w1;
}

// ---------------------------------------------------------------------------
// Merged init: zero vmax + wmax; last block reduces |bv|
// ---------------------------------------------------------------------------
__global__ void __launch_bounds__(256) init_kernel(const float* __restrict__ bv) {
    const int blk = blockIdx.x;
    const int tid = threadIdx.x;
    const int i = blk * 256 + tid;
    if (i < Mq) g_vmax[i] = 0u;
    if (i < 4 * Dq) g_wmax[i] = 0u;
    if (blk == gridDim.x - 1) {
        float mx = fmaxf(fmaxf(fabsf(bv[tid]), fabsf(bv[tid + 256])), fabsf(bv[tid + 512]));
        #pragma unroll
        for (int o = 16; o > 0; o >>= 1)
            mx = fmaxf(mx, __shfl_xor_sync(0xFFFFFFFFu, mx, o));
        __shared__ float rm[8];
        if ((tid & 31) == 0) rm[tid >> 5] = mx;
        __syncthreads();
        if (tid == 0) {
            mx = fmaxf(fmaxf(fmaxf(rm[0], rm[1]), fmaxf(rm[2], rm[3])),
                       fmaxf(fmaxf(rm[4], rm[5]), fmaxf(rm[6], rm[7])));
            g_bvmax = mx;
        }
    }
}

// ---------------------------------------------------------------------------
// Weight absmax per output column (atomicMax on positive float bits).
// Zeroes handled here too (runs on its own stream): first y-block writes 0
// via plain atomic exch ordering — instead we zero inline: use atomicMax
// against 0-initialized memory. To stay stream-local, wmax zeroing is done
// by a dedicated grid-stride pass below.
// ---------------------------------------------------------------------------
__global__ void __launch_bounds__(256) wzero_kernel() {
    const int i = blockIdx.x * 256 + threadIdx.x;
    if (i < 4 * Dq) g_wmax[i] = 0u;
}
__global__ void __launch_bounds__(256) wmax_kernel(
    const float* __restrict__ Wq, const float* __restrict__ Wk,
    const float* __restrict__ Wv, const float* __restrict__ Wo)
{
    const int w = blockIdx.z;
    const float* W = (w == 0) ? Wq : (w == 1) ? Wk : (w == 2) ? Wv : Wo;
    const int n = blockIdx.x * 256 + threadIdx.x;
    const int k0 = blockIdx.y * 96;
    float mx = 0.f;
    for (int j = 0; j < 96; j++)
        mx = fmaxf(mx, fabsf(W[(size_t)(k0 + j) * Dq + n]));
    atomicMax(&g_wmax[w * Dq + n], __float_as_uint(mx));
}

// ---------------------------------------------------------------------------
// init for the x-path stream: zero vmax + bvmax only
// ---------------------------------------------------------------------------
__global__ void __launch_bounds__(256) vinit_kernel(const float* __restrict__ bv) {
    const int blk = blockIdx.x;
    const int tid = threadIdx.x;
    const int i = blk * 256 + tid;
    if (i < Mq) g_vmax[i] = 0u;
    if (blk == gridDim.x - 1) {
        float mx = fmaxf(fmaxf(fabsf(bv[tid]), fabsf(bv[tid + 256])), fabsf(bv[tid + 512]));
        #pragma unroll
        for (int o = 16; o > 0; o >>= 1)
            mx = fmaxf(mx, __shfl_xor_sync(0xFFFFFFFFu, mx, o));
        __shared__ float rm[8];
        if ((tid & 31) == 0) rm[tid >> 5] = mx;
        __syncthreads();
        if (tid == 0) {
            mx = fmaxf(fmaxf(fmaxf(rm[0], rm[1]), fmaxf(rm[2], rm[3])),
                       fmaxf(fmaxf(rm[4], rm[5]), fmaxf(rm[6], rm[7])));
            g_bvmax = mx;
        }
    }
}

// ---------------------------------------------------------------------------
// Weight quantize + transpose: out[n][k] digits
// ---------------------------------------------------------------------------
__global__ void __launch_bounds__(256) wquant_kernel(
    const float* __restrict__ Wq, const float* __restrict__ Wk,
    const float* __restrict__ Wv, const float* __restrict__ Wo)
{
    __shared__ float t[32][33];
    const int w = blockIdx.z;
    const float* W = (w == 0) ? Wq : (w == 1) ? Wk : (w == 2) ? Wv : Wo;
    const int n0 = blockIdx.x * 32, k0 = blockIdx.y * 32;
    const int tx = threadIdx.x & 31, ty = threadIdx.x >> 5;

    #pragma unroll
    for (int i = 0; i < 4; i++)
        t[ty + i * 8][tx] = W[(size_t)(k0 + ty + i * 8) * Dq + n0 + tx];
    __syncthreads();
    #pragma unroll
    for (int i = 0; i < 4; i++) {
        const int n = n0 + ty + i * 8;
        const float mx = __uint_as_float(g_wmax[w * Dq + n]);
        const float inv = (mx > 0.f) ? (QMAX / mx) : 0.f;
        if (k0 == 0 && tx == 0)
            g_wsc[w * Dq + n] = (mx > 0.f) ? (mx / QMAX) : 0.f;
        const float val = t[tx][ty + i * 8];        // W[k0+tx][n]
        const int q = __float2int_rn(val * inv);
        const int a0 = (q + 64) >> 7;
        const int a1 = q - (a0 << 7);
        const size_t o = (size_t)(w * Dq + n) * Dq + k0 + tx;
        g_wq0[o] = (int8_t)a0;
        g_wq1[o] = (int8_t)a1;
    }
}

// ---------------------------------------------------------------------------
// int8 tensor-core GEMM (R7-proven): C[64 x 128] = A @ W^T, 3 IMMA products.
// mode 0: outputs Q|K|V as fp16 (+bias) and V-row absmax atomics, grid (18, 512)
// mode 1: g_Y = C + bo + resid (fp32), grid (6, 512)
// ---------------------------------------------------------------------------
__global__ void __launch_bounds__(256, 2) ig_gemm_kernel(
    const int8_t* __restrict__ Aq0, const int8_t* __restrict__ Aq1,
    const float* __restrict__ Asc,
    const float* __restrict__ bias_a, const float* __restrict__ bias_b,
    const float* __restrict__ bias_c, const float* __restrict__ resid,
    int wbase, int mode)
{
    extern __shared__ __align__(128) char smem_raw[];
    const uint32_t base = smem_u32(smem_raw);

    const int tid  = threadIdx.x;
    const int wid  = tid >> 5;
    const int lane = tid & 31;
    const int m0 = blockIdx.y * BM;
    const int bx = blockIdx.x;
    const int nrow0 = wbase + bx * BN;

    const int wm0 = (wid & 1) * 32;          // 2 warps in M
    const int wn0 = (wid >> 1) * 32;         // 4 warps in N

    const int rA   = tid >> 2;
    const int sgA  = tid & 3;
    const uint32_t soA = (uint32_t)(rA * 64 + ((sgA ^ ((rA >> 1) & 3)) << 4));

    auto load_stage = [&](int c, int s) {
        const int k0 = c * BK;
        const uint32_t sb = base + (uint32_t)s * STAGE_B;
        cp16(sb + A0_OFF + soA, Aq0 + (size_t)(m0 + rA) * Dq + k0 + sgA * 16);
        cp16(sb + A1_OFF + soA, Aq1 + (size_t)(m0 + rA) * Dq + k0 + sgA * 16);
        #pragma unroll
        for (int half = 0; half < 2; half++) {
            const int u = tid + half * 256;
            const int rB = u >> 2, sgB = u & 3;
            const uint32_t soB = (uint32_t)(rB * 64 + ((sgB ^ ((rB >> 1) & 3)) << 4));
            cp16(sb + B0_OFF + soB, g_wq0 + (size_t)(nrow0 + rB) * Dq + k0 + sgB * 16);
            cp16(sb + B1_OFF + soB, g_wq1 + (size_t)(nrow0 + rB) * Dq + k0 + sgB * 16);
        }
        cp_commit();
    };

    int hi[2][4][4], mid[2][4][4];
    #pragma unroll
    for (int mi = 0; mi < 2; mi++)
        #pragma unroll
        for (int n8 = 0; n8 < 4; n8++)
            #pragma unroll
            for (int j = 0; j < 4; j++) { hi[mi][n8][j] = 0; mid[mi][n8][j] = 0; }

    const int lrow = (lane & 7) + ((lane >> 3) & 1) * 8;
    const int lkseg = (lane >> 4);

    load_stage(0, 0);
    load_stage(1, 1);

    for (int c = 0; c < NCHUNK; c++) {
        if (c + 1 < NCHUNK) cp_wait1();
        else                cp_wait0();
        __syncthreads();
        if (c + 2 < NCHUNK) load_stage(c + 2, (c + 2) % NSTAGE);

        const uint32_t sb = base + (uint32_t)(c % NSTAGE) * STAGE_B;
        const uint32_t sA0 = sb + A0_OFF, sA1 = sb + A1_OFF;
        const uint32_t sB0 = sb + B0_OFF, sB1 = sb + B1_OFF;

        #pragma unroll
        for (int ks = 0; ks < 2; ks++) {
            const int segk = ks * 2 + lkseg;
            uint32_t a0[2][4], a1[2][4];
            #pragma unroll
            for (int mi = 0; mi < 2; mi++) {
                const int row = wm0 + mi * 16 + lrow;
                const uint32_t ro = (uint32_t)(row * 64 + ((segk ^ ((row >> 1) & 3)) << 4));
                ldsm_x4(a0[mi], sA0 + ro);
                ldsm_x4(a1[mi], sA1 + ro);
            }
            #pragma unroll
            for (int g = 0; g < 2; g++) {
                uint32_t b0[4], b1[4];
                const int row = wn0 + g * 16 + lrow;
                const uint32_t ro = (uint32_t)(row * 64 + ((segk ^ ((row >> 1) & 3)) << 4));
                ldsm_x4(b0, sB0 + ro);
                ldsm_x4(b1, sB1 + ro);
                #pragma unroll
                for (int mi = 0; mi < 2; mi++) {
                    imma(hi[mi][g * 2 + 0], a0[mi], b0[0], b0[2]);
                    imma(hi[mi][g * 2 + 1], a0[mi], b0[1], b0[3]);
                    imma(mid[mi][g * 2 + 0], a0[mi], b1[0], b1[2]);
                    imma(mid[mi][g * 2 + 1], a0[mi], b1[1], b1[3]);
                    imma(mid[mi][g * 2 + 0], a1[mi], b0[0], b0[2]);
                    imma(mid[mi][g * 2 + 1], a1[mi], b0[1], b0[3]);
                }
            }
        }
    }

    // ---- epilogue ----
    const int qr = lane >> 2;
    const int qc = (lane & 3) * 2;

    if (mode == 0) {
        const int sel = bx / 6;
        const int n0in = (bx % 6) * BN;
        __half* outp = (sel == 0) ? g_Q : (sel == 1) ? g_K : g_V;
        const float* bias = (sel == 0) ? bias_a : (sel == 1) ? bias_b : bias_c;
        #pragma unroll
        for (int mi = 0; mi < 2; mi++) {
            #pragma unroll
            for (int half = 0; half < 2; half++) {
                const int m = m0 + wm0 + mi * 16 + qr + half * 8;
                const float sa128 = Asc[m] * 128.f;
                float lmax = 0.f;
                #pragma unroll
                for (int n8 = 0; n8 < 4; n8++) {
                    const int nl = wn0 + n8 * 8 + qc;
                    const float sb0 = g_wsc[nrow0 + nl] * sa128;
                    const float sb1 = g_wsc[nrow0 + nl + 1] * sa128;
                    const int n = n0in + nl;
                    const size_t o = (size_t)m * Dq + n;
                    const int t0 = hi[mi][n8][half * 2 + 0] * 128 + mid[mi][n8][half * 2 + 0];
                    const int t1 = hi[mi][n8][half * 2 + 1] * 128 + mid[mi][n8][half * 2 + 1];
                    float2 v;
                    v.x = (float)t0 * sb0 + bias[n];
                    v.y = (float)t1 * sb1 + bias[n + 1];
                    *(__half2*)(outp + o) = __float22half2_rn(v);
                    lmax = fmaxf(lmax, fmaxf(fabsf(v.x), fabsf(v.y)));
                }
                if (sel == 2) {
                    lmax = fmaxf(lmax, __shfl_xor_sync(0xFFFFFFFFu, lmax, 1));
                    lmax = fmaxf(lmax, __shfl_xor_sync(0xFFFFFFFFu, lmax, 2));
                    if ((lane & 3) == 0)
                        atomicMax(&g_vmax[m], __float_as_uint(lmax));
                }
            }
        }
    } else {
        const int n0in = bx * BN;
        const float* bias = bias_a;
        #pragma unroll
        for (int mi = 0; mi < 2; mi++) {
            #pragma unroll
            for (int half = 0; half < 2; half++) {
                const int m = m0 + wm0 + mi * 16 + qr + half * 8;
                const float sa128 = Asc[m] * 128.f;
                #pragma unroll
                for (int n8 = 0; n8 < 4; n8++) {
                    const int nl = wn0 + n8 * 8 + qc;
                    const float sb0 = g_wsc[nrow0 + nl] * sa128;
                    const float sb1 = g_wsc[nrow0 + nl + 1] * sa128;
                    const int n = n0in + nl;
                    const size_t o = (size_t)m * Dq + n;
                    const int t0 = hi[mi][n8][half * 2 + 0] * 128 + mid[mi][n8][half * 2 + 0];
                    const int t1 = hi[mi][n8][half * 2 + 1] * 128 + mid[mi][n8][half * 2 + 1];
                    float2 v;
                    v.x = (float)t0 * sb0 + bias[n] + resid[o];
                    v.y = (float)t1 * sb1 + bias[n + 1] + resid[o + 1];
                    *(float2*)(g_Y + o) = v;
                }
            }
        }
    }
}

// ---------------------------------------------------------------------------
// Banded attention: single-phase K+V staging, Q prefetched before barrier,
// inline vscale from the g_vmax window, int8 digit output.
// ---------------------------------------------------------------------------
#define AT_TS 128
#define AT_HALO 132
#define AT_ROWH 70            // halves per row stride (140 B -> conflict-free half2)
#define ATT_SMEM (2 * AT_HALO * AT_ROWH * 2)   // Ks + Vs = 36960 B

__global__ void __launch_bounds__(256) attn_kernel(
    const float* __restrict__ bk, const float* __restrict__ bv,
    int8_t* __restrict__ aq0, int8_t* __restrict__ aq1)
{
    extern __shared__ __half smh[];
    __half* Ks = smh;
    __half* Vs = smh + AT_HALO * AT_ROWH;

    const int by = blockIdx.y;
    const int b  = by / Hq;
    const int h  = by % Hq;
    const int s0 = blockIdx.x * AT_TS;

    const size_t basep = ((size_t)b * Sq) * Dq + h * DHq;
    const int tid = threadIdx.x;
    const int si  = tid >> 1;          // position within tile
    const int hh  = tid & 1;           // dim half
    const int row = b * Sq + s0 + si;

    // ---- prefetch Q (independent of smem) BEFORE staging/barrier ----
    const __half2* qrow = (const __half2*)(g_Q + (size_t)row * Dq + h * DHq + hh * 32);
    __half2 qh[16];
    #pragma unroll
    for (int d2 = 0; d2 < 16; d2++) qh[d2] = qrow[d2];

    // ---- stage K and V together (one barrier total) ----
    {
        const __half* Kg = g_K + basep;
        const __half* Vg = g_V + basep;
        const float* bks = bk + h * DHq;
        const float* bvs = bv + h * DHq;
        for (int idx = tid; idx < AT_HALO * 32; idx += 256) {
            const int r = idx >> 5;
            const int c2 = (idx & 31) * 2;
            const int gs = s0 - 2 + r;
            __half2 kv, vv;
            if (gs >= 0 && gs < Sq) {
                kv = *(const __half2*)(Kg + (size_t)gs * Dq + c2);
                vv = *(const __half2*)(Vg + (size_t)gs * Dq + c2);
            } else {
                kv = __float22half2_rn(*(const float2*)(bks + c2));
                vv = __float22half2_rn(*(const float2*)(bvs + c2));
            }
            *(__half2*)&Ks[r * AT_ROWH + c2] = kv;
            *(__half2*)&Vs[r * AT_ROWH + c2] = vv;
        }
    }
    __syncthreads();

    float2 qv[16];
    #pragma unroll
    for (int d2 = 0; d2 < 16; d2++) qv[d2] = __half22float2(qh[d2]);

    float sc[5];
    #pragma unroll
    for (int i = 0; i < 5; i++) {
        const __half2* krow = (const __half2*)&Ks[(si + i) * AT_ROWH + hh * 32];
        float s = 0.f;
        #pragma unroll
        for (int d2 = 0; d2 < 16; d2++) {
            const float2 kf = __half22float2(krow[d2]);
            s += qv[d2].x * kf.x + qv[d2].y * kf.y;
        }
        sc[i] = s;
    }
    #pragma unroll
    for (int i = 0; i < 5; i++)
        sc[i] += __shfl_xor_sync(0xFFFFFFFFu, sc[i], 1);

    float mx = sc[0];
    #pragma unroll
    for (int i = 1; i < 5; i++) mx = fmaxf(mx, sc[i]);
    float p[5], sum = 0.f;
    #pragma unroll
    for (int i = 0; i < 5; i++) {
        p[i] = __expf((sc[i] - mx) * 0.125f);
        sum += p[i];
    }
    const float inv = 1.f / sum;
    #pragma unroll
    for (int i = 0; i < 5; i++) p[i] *= inv;

    float2 o2[16];
    #pragma unroll
    for (int d2 = 0; d2 < 16; d2++) { o2[d2].x = 0.f; o2[d2].y = 0.f; }
    #pragma unroll
    for (int i = 0; i < 5; i++) {
        const __half2* vrow = (const __half2*)&Vs[(si + i) * AT_ROWH + hh * 32];
        const float pi = p[i];
        #pragma unroll
        for (int d2 = 0; d2 < 16; d2++) {
            const float2 vf = __half22float2(vrow[d2]);
            o2[d2].x += pi * vf.x;
            o2[d2].y += pi * vf.y;
        }
    }

    // ---- inline vscale: bound amax by the V-row window + |bv| ----
    const int sloc = s0 + si;
    float amax = g_bvmax;
    #pragma unroll
    for (int i = -2; i <= 2; i++) {
        const int ss = sloc + i;
        if (ss >= 0 && ss < Sq)
            amax = fmaxf(amax, __uint_as_float(g_vmax[(b << 12) + ss]));
    }
    if (amax <= 0.f) amax = 1e-20f;
    const float qinv = QMAX / amax;
    if (hh == 0) g_asc[row] = amax / QMAX;

    // ---- quantize in-register, write digits ----
    uint32_t p0[8], p1[8];
    #pragma unroll
    for (int d2 = 0; d2 < 8; d2++) {
        uint32_t w0 = 0, w1 = 0;
        #pragma unroll
        for (int j = 0; j < 2; j++) {
            const float2 o = o2[d2 * 2 + j];
            const int nx = __float2int_rn(o.x * qinv);
            const int ax0 = (nx + 64) >> 7;
            const int ax1 = nx - (ax0 << 7);
            const int ny = __float2int_rn(o.y * qinv);
            const int ay0 = (ny + 64) >> 7;
            const int ay1 = ny - (ay0 << 7);
            w0 |= ((uint32_t)(ax0 & 255) << (j * 16)) | ((uint32_t)(ay0 & 255) << (j * 16 + 8));
            w1 |= ((uint32_t)(ax1 & 255) << (j * 16)) | ((uint32_t)(ay1 & 255) << (j * 16 + 8));
        }
        p0[d2] = w0;
        p1[d2] = w1;
    }
    const size_t obase = (size_t)row * Dq + h * DHq + hh * 32;
    *(uint4*)(aq0 + obase)      = make_uint4(p0[0], p0[1], p0[2], p0[3]);
    *(uint4*)(aq0 + obase + 16) = make_uint4(p0[4], p0[5], p0[6], p0[7]);
    *(uint4*)(aq1 + obase)      = make_uint4(p1[0], p1[1], p1[2], p1[3]);
    *(uint4*)(aq1 + obase + 16) = make_uint4(p1[4], p1[5], p1[6], p1[7]);
}

// ---------------------------------------------------------------------------
// LayerNorm over last dim (768), float4 loads, 192 threads
// ---------------------------------------------------------------------------
__global__ void __launch_bounds__(192) ln_kernel(
    const float* __restrict__ gamma, const float* __restrict__ beta,
    float* __restrict__ outp)
{
    const int row = blockIdx.x;
    const float* y = g_Y + (size_t)row * Dq;
    const int tid = threadIdx.x;

    float4 v = *(const float4*)(y + tid * 4);
    float s  = v.x + v.y + v.z + v.w;
    float ss = v.x * v.x + v.y * v.y + v.z * v.z + v.w * v.w;
    #pragma unroll
    for (int o = 16; o > 0; o >>= 1) {
        s  += __shfl_xor_sync(0xFFFFFFFFu, s,  o);
        ss += __shfl_xor_sync(0xFFFFFFFFu, ss, o);
    }
    __shared__ float rs[6], rss[6];
    const int w = tid >> 5;
    if ((tid & 31) == 0) { rs[w] = s; rss[w] = ss; }
    __syncthreads();
    s  = rs[0] + rs[1] + rs[2] + rs[3] + rs[4] + rs[5];
    ss = rss[0] + rss[1] + rss[2] + rss[3] + rss[4] + rss[5];

    const float mu   = s * (1.f / 768.f);
    const float var  = ss * (1.f / 768.f) - mu * mu;
    const float rstd = rsqrtf(var + 1e-5f);

    const float4 g = *(const float4*)(gamma + tid * 4);
    const float4 be = *(const float4*)(beta + tid * 4);
    float4 o;
    o.x = (v.x - mu) * rstd * g.x + be.x;
    o.y = (v.y - mu) * rstd * g.y + be.y;
    o.z = (v.z - mu) * rstd * g.z + be.z;
    o.w = (v.w - mu) * rstd * g.w + be.w;
    *(float4*)(outp + (size_t)row * Dq + tid * 4) = o;
}

// ---------------------------------------------------------------------------
// Launch — prologue forked across two streams (x-path || weights-path).
// Streams/events created on the first (uncaptured) correctness call.
// ---------------------------------------------------------------------------
extern "C" void kernel_launch(void* const* d_in, const int* in_sizes, int n_in,
                              void* d_out, int out_size)
{
    const float* x     = (const float*)d_in[0];
    const float* Wq    = (const float*)d_in[1];
    const float* bq    = (const float*)d_in[2];
    const float* Wk    = (const float*)d_in[3];
    const float* bk    = (const float*)d_in[4];
    const float* Wv    = (const float*)d_in[5];
    const float* bv    = (const float*)d_in[6];
    const float* Wo    = (const float*)d_in[7];
    const float* bo    = (const float*)d_in[8];
    const float* gamma = (const float*)d_in[9];
    const float* beta  = (const float*)d_in[10];
    float* out = (float*)d_out;

    static cudaStream_t s1 = nullptr;
    static cudaEvent_t evFork = nullptr, evJoin = nullptr;
    static int configured = 0;
    if (!configured) {
        cudaFuncSetAttribute(ig_gemm_kernel,
                             cudaFuncAttributeMaxDynamicSharedMemorySize, GEMM_SMEM);
        cudaFuncSetAttribute(attn_kernel,
                             cudaFuncAttributeMaxDynamicSharedMemorySize, ATT_SMEM);
        cudaStreamCreateWithFlags(&s1, cudaStreamNonBlocking);
        cudaEventCreateWithFlags(&evFork, cudaEventDisableTiming);
        cudaEventCreateWithFlags(&evJoin, cudaEventDisableTiming);
        configured = 1;
    }

    int8_t *xq0, *xq1, *aq0, *aq1;
    float *xsc, *asc;
    cudaGetSymbolAddress((void**)&xq0, g_xq0);
    cudaGetSymbolAddress((void**)&xq1, g_xq1);
    cudaGetSymbolAddress((void**)&xsc, g_xsc);
    cudaGetSymbolAddress((void**)&aq0, g_aq0);
    cudaGetSymbolAddress((void**)&aq1, g_aq1);
    cudaGetSymbolAddress((void**)&asc, g_asc);

    // ---- fork: weights-path on s1, x-path on the main stream ----
    cudaEventRecord(evFork, 0);
    cudaStreamWaitEvent(s1, evFork, 0);

    // weights path (s1): zero wmax -> wmax -> wquant
    wzero_kernel<<<12, 256, 0, s1>>>();
    wmax_kernel<<<dim3(3, 8, 4), 256, 0, s1>>>(Wq, Wk, Wv, Wo);
    wquant_kernel<<<dim3(24, 24, 4), 256, 0, s1>>>(Wq, Wk, Wv, Wo);
    cudaEventRecord(evJoin, s1);

    // x path (main stream): vmax init + bvmax, x quantization
    vinit_kernel<<<Mq / 256, 256>>>(bv);
    quant_rows_kernel<<<Mq, 192>>>(x, xq0, xq1, xsc);

    // join before QKV GEMM (needs both xq and wq)
    cudaStreamWaitEvent(0, evJoin, 0);

    // 1) QKV projections (fp16 out, + V row absmax atomics)
    ig_gemm_kernel<<<dim3(18, Mq / BM), 256, GEMM_SMEM>>>(
        xq0, xq1, xsc, bq, bk, bv, nullptr, 0, 0);

    // 2) fused attention + inline vscale + quant
    attn_kernel<<<dim3(Sq / AT_TS, Bq * Hq), 256, ATT_SMEM>>>(bk, bv, aq0, aq1);

    // 3) O projection + bias + residual -> g_Y
    ig_gemm_kernel<<<dim3(6, Mq / BM), 256, GEMM_SMEM>>>(
        aq0, aq1, asc, bo, nullptr, nullptr, x, 3 * Dq, 1);

    // 4) LayerNorm -> d_out
    ln_kernel<<<Mq, 192>>>(gamma, beta, out);
}